// round 6
// baseline (speedup 1.0000x reference)
#include <cuda_runtime.h>
#include <math.h>

// ---------------------------------------------------------------------------
// PainHead: per-segment Conv1d(K=9) -> ReLU -> BN  (x2)  -> Linear(2) -> softmax
// N=8192 tokens, D_IN=600, D_H=2048, NSEG=64, segment_key sorted.
//
// Round 4 fix: segment_key is int32 (JAX x64 disabled), NOT int64. Reading it
// as long long corrupted masks for the first half of tokens and read OOB for
// the second half -> rel_err 0.68. Everything else unchanged from the f32x2
// packed-FMA SIMT GEMM baseline.
// ---------------------------------------------------------------------------

#define N_TOK 8192
#define DIN   600
#define DINP  608      // DIN padded to multiple of BK, zero-filled
#define DH    2048
#define KW    9
#define BN_EPS 1e-5f

#define BM 128
#define BN 128
#define BK 16
#define AROWS   (BM + 8)   // 136 source rows cover all 9 shifts
#define ASTRIDE 137        // padded stride -> conflict-free smem writes

// ---- scratch (static __device__ — no allocations allowed) ----
__device__ float    g_h1[(size_t)N_TOK * DH];
__device__ float    g_h2[(size_t)N_TOK * DH];
__device__ float    g_w1t[(size_t)KW * DINP * DH];   // [k][c][o]
__device__ float    g_w2t[(size_t)KW * DH * DH];     // [k][c][o]
__device__ unsigned g_mask[N_TOK];                   // bit k: seg[i+k-4]==seg[i]

// ---- packed fp32x2 helpers (sm_103a; ptxas never auto-fuses these) ----
__device__ __forceinline__ unsigned long long pack2(float a, float b) {
    unsigned long long r;
    asm("mov.b64 %0, {%1, %2};" : "=l"(r) : "f"(a), "f"(b));
    return r;
}
__device__ __forceinline__ void fma2(unsigned long long& d,
                                     unsigned long long a, unsigned long long b) {
    asm("fma.rn.f32x2 %0, %1, %2, %0;" : "+l"(d) : "l"(a), "l"(b));
}
__device__ __forceinline__ void unpack2(float& lo, float& hi, unsigned long long v) {
    asm("mov.b64 {%0, %1}, %2;" : "=f"(lo), "=f"(hi) : "l"(v));
}

// ---------------------------------------------------------------------------
// Segment-validity bitmask per token. segment_key is INT32.
// ---------------------------------------------------------------------------
__global__ void mask_kernel(const int* __restrict__ seg,
                            unsigned* __restrict__ bits) {
    int i = blockIdx.x * blockDim.x + threadIdx.x;
    if (i >= N_TOK) return;
    int s = seg[i];
    unsigned b = 0;
#pragma unroll
    for (int k = 0; k < KW; ++k) {
        int j = i + k - KW / 2;
        if (j >= 0 && j < N_TOK && seg[j] == s) b |= (1u << k);
    }
    bits[i] = b;
}

// ---------------------------------------------------------------------------
// Weight reshape: w[o][c][k] -> wt[k][c][o]  (zero-pad c to CdimP).
// ---------------------------------------------------------------------------
__global__ void wtrans_kernel(const float* __restrict__ w, float* __restrict__ wt,
                              int Cdim, int CdimP) {
    size_t idx = (size_t)blockIdx.x * blockDim.x + threadIdx.x;
    size_t total = (size_t)KW * CdimP * DH;
    if (idx >= total) return;
    int o = (int)(idx % DH);
    size_t t = idx / DH;
    int c = (int)(t % CdimP);
    int k = (int)(t / CdimP);
    float v = 0.0f;
    if (c < Cdim) v = w[((size_t)o * Cdim + c) * KW + k];
    wt[idx] = v;
}

// ---------------------------------------------------------------------------
// Conv-GEMM: out[i][o] = BN(ReLU(bias[o] + sum_{k,c} mask(i,k)*A[i+k-4][c]*w[o][c][k]))
// Block: 128x128 C-tile, 256 threads, 8x8 micro-tile per thread, f32x2 accum.
// ---------------------------------------------------------------------------
__global__ __launch_bounds__(256, 2) void conv_gemm_kernel(
    const float* __restrict__ A, int Cdim, int CdimP,
    const float* __restrict__ Wt,            // [k][CdimP][DH]
    const unsigned* __restrict__ maskbits,
    const float* __restrict__ bias, const float* __restrict__ gamma,
    const float* __restrict__ beta, const float* __restrict__ mean,
    const float* __restrict__ var,
    float* __restrict__ outp)
{
    __shared__ __align__(16) float As[BK][ASTRIDE];
    __shared__ __align__(16) float Bs[BK][BN];

    const int tid  = threadIdx.x;
    const int tx   = tid & 15;       // output-col group
    const int ty   = tid >> 4;       // output-row group
    const int i0   = blockIdx.y * BM;
    const int o0   = blockIdx.x * BN;
    const int row0 = ty * 8;
    const int col0 = tx * 8;

    unsigned mbits[8];
#pragma unroll
    for (int m = 0; m < 8; ++m) mbits[m] = maskbits[i0 + row0 + m];

    unsigned long long acc[8][4];
#pragma unroll
    for (int m = 0; m < 8; ++m)
#pragma unroll
        for (int p = 0; p < 4; ++p) acc[m][p] = 0ULL;   // (0.f, 0.f)

    const int nChunks = CdimP / BK;
    for (int cc = 0; cc < nChunks; ++cc) {
        const int c0 = cc * BK;
        __syncthreads();                       // everyone done with previous tiles
        // load extended A tile: source rows i0-4 .. i0+BM+3
        for (int idx = tid; idx < AROWS * BK; idx += 256) {
            int c  = idx & (BK - 1);
            int r  = idx >> 4;
            int gi = i0 - 4 + r;
            int cg = c0 + c;
            float v = 0.0f;
            if (gi >= 0 && gi < N_TOK && cg < Cdim)
                v = A[(size_t)gi * Cdim + cg];
            As[c][r] = v;
        }
        for (int k = 0; k < KW; ++k) {
            __syncthreads();                   // As visible / previous Bs consumed
            const float* src = Wt + ((size_t)k * CdimP + c0) * DH + o0;
            for (int idx = tid; idx < BK * BN / 4; idx += 256) {
                int o4 = idx & 31;
                int c  = idx >> 5;
                float4 v = *(const float4*)(src + (size_t)c * DH + o4 * 4);
                *(float4*)&Bs[c][o4 * 4] = v;
            }
            __syncthreads();                   // Bs visible

            float mfs[8];
#pragma unroll
            for (int m = 0; m < 8; ++m)
                mfs[m] = ((mbits[m] >> k) & 1u) ? 1.0f : 0.0f;

#pragma unroll
            for (int c = 0; c < BK; ++c) {
                ulonglong2 bb0 = *(const ulonglong2*)&Bs[c][col0];
                ulonglong2 bb1 = *(const ulonglong2*)&Bs[c][col0 + 4];
                const float* ar = &As[c][row0 + k];
#pragma unroll
                for (int m = 0; m < 8; ++m) {
                    float a = ar[m] * mfs[m];
                    unsigned long long a2 = pack2(a, a);
                    fma2(acc[m][0], a2, bb0.x);
                    fma2(acc[m][1], a2, bb0.y);
                    fma2(acc[m][2], a2, bb1.x);
                    fma2(acc[m][3], a2, bb1.y);
                }
            }
        }
    }

    // ---- epilogue: bias + ReLU + BatchNorm(eval) ----
    float sc[8], sh[8], bi[8];
#pragma unroll
    for (int j = 0; j < 8; ++j) {
        int o = o0 + col0 + j;
        float s = gamma[o] * rsqrtf(var[o] + BN_EPS);
        sc[j] = s;
        sh[j] = beta[o] - mean[o] * s;
        bi[j] = bias[o];
    }
#pragma unroll
    for (int m = 0; m < 8; ++m) {
        int row = i0 + row0 + m;
        float v[8];
#pragma unroll
        for (int p = 0; p < 4; ++p) unpack2(v[2 * p], v[2 * p + 1], acc[m][p]);
#pragma unroll
        for (int j = 0; j < 8; ++j) {
            float t = v[j] + bi[j];
            t = fmaxf(t, 0.0f);
            v[j] = t * sc[j] + sh[j];
        }
        float* dst = outp + (size_t)row * DH + o0 + col0;
        *(float4*)(dst)     = make_float4(v[0], v[1], v[2], v[3]);
        *(float4*)(dst + 4) = make_float4(v[4], v[5], v[6], v[7]);
    }
}

// ---------------------------------------------------------------------------
// Final linear (2 outputs) + softmax. One warp per token row.
// Output layout: [output_pain (N,2)] then [pain_pred (N,2)], both row-major.
// ---------------------------------------------------------------------------
__global__ void final_kernel(const float* __restrict__ h,
                             const float* __restrict__ wl,
                             const float* __restrict__ bl,
                             float* __restrict__ out)
{
    int gwarp = (blockIdx.x * blockDim.x + threadIdx.x) >> 5;
    int lane  = threadIdx.x & 31;
    if (gwarp >= N_TOK) return;

    const float4* hv = (const float4*)(h + (size_t)gwarp * DH);
    const float4* w0 = (const float4*)(wl);
    const float4* w1 = (const float4*)(wl + DH);

    float s0 = 0.0f, s1 = 0.0f;
    for (int j = lane; j < DH / 4; j += 32) {
        float4 a  = hv[j];
        float4 c0 = w0[j];
        float4 c1 = w1[j];
        s0 += a.x * c0.x + a.y * c0.y + a.z * c0.z + a.w * c0.w;
        s1 += a.x * c1.x + a.y * c1.y + a.z * c1.z + a.w * c1.w;
    }
#pragma unroll
    for (int off = 16; off > 0; off >>= 1) {
        s0 += __shfl_xor_sync(0xFFFFFFFFu, s0, off);
        s1 += __shfl_xor_sync(0xFFFFFFFFu, s1, off);
    }
    if (lane == 0) {
        float z0 = s0 + bl[0];
        float z1 = s1 + bl[1];
        float mx = fmaxf(z0, z1);
        float e0 = expf(z0 - mx);
        float e1 = expf(z1 - mx);
        float inv = 1.0f / (e0 + e1);
        out[(size_t)gwarp * 2 + 0] = z0;
        out[(size_t)gwarp * 2 + 1] = z1;
        out[(size_t)2 * N_TOK + (size_t)gwarp * 2 + 0] = e0 * inv;
        out[(size_t)2 * N_TOK + (size_t)gwarp * 2 + 1] = e1 * inv;
    }
}

// ---------------------------------------------------------------------------
extern "C" void kernel_launch(void* const* d_in, const int* in_sizes, int n_in,
                              void* d_out, int out_size) {
    const float* x   = (const float*)d_in[0];
    const int*   seg = (const int*)d_in[1];      // int32! (JAX x64 disabled)
    const float* w1  = (const float*)d_in[2];
    const float* b1  = (const float*)d_in[3];
    const float* g1  = (const float*)d_in[4];
    const float* be1 = (const float*)d_in[5];
    const float* m1  = (const float*)d_in[6];
    const float* v1  = (const float*)d_in[7];
    const float* w2  = (const float*)d_in[8];
    const float* b2  = (const float*)d_in[9];
    const float* g2  = (const float*)d_in[10];
    const float* be2 = (const float*)d_in[11];
    const float* m2  = (const float*)d_in[12];
    const float* v2  = (const float*)d_in[13];
    const float* wl  = (const float*)d_in[14];
    const float* bl  = (const float*)d_in[15];
    float* out = (float*)d_out;

    float *h1, *h2, *w1t, *w2t;
    unsigned* mask;
    cudaGetSymbolAddress((void**)&h1,   g_h1);
    cudaGetSymbolAddress((void**)&h2,   g_h2);
    cudaGetSymbolAddress((void**)&w1t,  g_w1t);
    cudaGetSymbolAddress((void**)&w2t,  g_w2t);
    cudaGetSymbolAddress((void**)&mask, g_mask);

    mask_kernel<<<(N_TOK + 255) / 256, 256>>>(seg, mask);

    {
        size_t total1 = (size_t)KW * DINP * DH;
        wtrans_kernel<<<(unsigned)((total1 + 255) / 256), 256>>>(w1, w1t, DIN, DINP);
        size_t total2 = (size_t)KW * DH * DH;
        wtrans_kernel<<<(unsigned)((total2 + 255) / 256), 256>>>(w2, w2t, DH, DH);
    }

    dim3 grid(DH / BN, N_TOK / BM);
    conv_gemm_kernel<<<grid, 256>>>(x, DIN, DINP, w1t, mask,
                                    b1, g1, be1, m1, v1, h1);
    conv_gemm_kernel<<<grid, 256>>>(h1, DH, DH, w2t, mask,
                                    b2, g2, be2, m2, v2, h2);

    final_kernel<<<(N_TOK * 32 + 127) / 128, 128>>>(h2, wl, bl, out);
}

// round 10
// speedup vs baseline: 3.2248x; 3.2248x over previous
#include <cuda_runtime.h>
#include <cuda_bf16.h>
#include <cstdint>
#include <math.h>

// ---------------------------------------------------------------------------
// PainHead via warp-level bf16 mma.sync (m16n8k16) split-GEMM.
// tcgen05 is NOT available: harness compiles PTX at target sm_103 (no 'a'),
// and tcgen05 is arch-specific. mma.sync/ldmatrix are baseline PTX and still
// use the tensor pipe.
//
// out[i,o] = BN(ReLU(b[o] + sum_{k,c} mask(i,k) * A[i+k-4,c] * W[o,c,k]))
// fp32 recovered from bf16 via hi/lo split: D = Ah*Wh + Ah*Wl + Al*Wh.
// CTA tile: 128 tokens x 128 outputs; K-loop: 64-ch chunks x 9 taps.
// Tap shift folded into ldmatrix addressing; segment mask applied on A frags.
// (Round 8: resubmission — previous round died to a container infra failure.)
// ---------------------------------------------------------------------------

#define N_TOK 8192
#define DIN   600
#define CP1   640
#define DH    2048
#define KW    9
#define BN_EPS 1e-5f

// ---------------- device scratch ----------------
__device__ __nv_bfloat16 g_xh[(size_t)N_TOK * CP1];
__device__ __nv_bfloat16 g_xl[(size_t)N_TOK * CP1];
__device__ __nv_bfloat16 g_w1h[(size_t)KW * DH * CP1];
__device__ __nv_bfloat16 g_w1l[(size_t)KW * DH * CP1];
__device__ __nv_bfloat16 g_w2h[(size_t)KW * DH * DH];
__device__ __nv_bfloat16 g_w2l[(size_t)KW * DH * DH];
__device__ __nv_bfloat16 g_h1h[(size_t)N_TOK * DH];
__device__ __nv_bfloat16 g_h1l[(size_t)N_TOK * DH];
__device__ float         g_h2[(size_t)N_TOK * DH];
__device__ unsigned      g_mask[N_TOK];

// ---------------- warp MMA helpers ----------------
__device__ __forceinline__ uint32_t smem_u32(const void* p) {
    uint32_t a;
    asm("{ .reg .u64 t; cvta.to.shared.u64 t, %1; cvt.u32.u64 %0, t; }"
        : "=r"(a) : "l"(p));
    return a;
}
__device__ __forceinline__ void ldm4(uint32_t* r, uint32_t addr) {
    asm volatile("ldmatrix.sync.aligned.m8n8.x4.shared.b16 {%0,%1,%2,%3}, [%4];"
                 : "=r"(r[0]), "=r"(r[1]), "=r"(r[2]), "=r"(r[3]) : "r"(addr));
}
__device__ __forceinline__ void mma16816(float* d, const uint32_t* a,
                                         uint32_t b0, uint32_t b1) {
    asm volatile(
        "mma.sync.aligned.m16n8k16.row.col.f32.bf16.bf16.f32 "
        "{%0,%1,%2,%3}, {%4,%5,%6,%7}, {%8,%9}, {%0,%1,%2,%3};"
        : "+f"(d[0]), "+f"(d[1]), "+f"(d[2]), "+f"(d[3])
        : "r"(a[0]), "r"(a[1]), "r"(a[2]), "r"(a[3]), "r"(b0), "r"(b1));
}

// ---------------- smem layout ----------------
// A ext: 2 planes x 136 rows x 128B = 34816
// B:     2 stages x 2 planes x 128 rows x 128B = 65536
#define SM_A      0
#define SM_B      34816
#define SMEM_TOTAL 100352

// ---------------------------------------------------------------------------
__global__ void mask_kernel(const int* __restrict__ seg, unsigned* __restrict__ bits) {
    int i = blockIdx.x * blockDim.x + threadIdx.x;
    if (i >= N_TOK) return;
    int s = seg[i];
    unsigned b = 0;
#pragma unroll
    for (int k = 0; k < KW; ++k) {
        int j = i + k - KW / 2;
        if (j >= 0 && j < N_TOK && seg[j] == s) b |= (1u << k);
    }
    bits[i] = b;
}

__global__ void split_x_kernel(const float* __restrict__ x,
                               __nv_bfloat16* __restrict__ xh,
                               __nv_bfloat16* __restrict__ xl) {
    size_t idx = (size_t)blockIdx.x * blockDim.x + threadIdx.x;
    if (idx >= (size_t)N_TOK * CP1) return;
    int c = (int)(idx % CP1);
    int r = (int)(idx / CP1);
    float v = (c < DIN) ? x[(size_t)r * DIN + c] : 0.0f;
    __nv_bfloat16 hi = __float2bfloat16(v);
    __nv_bfloat16 lo = __float2bfloat16(v - __bfloat162float(hi));
    xh[idx] = hi; xl[idx] = lo;
}

__global__ void split_w_kernel(const float* __restrict__ w,
                               __nv_bfloat16* __restrict__ wh,
                               __nv_bfloat16* __restrict__ wl,
                               int C, int cpad) {
    size_t idx = (size_t)blockIdx.x * blockDim.x + threadIdx.x;
    size_t total = (size_t)KW * DH * cpad;
    if (idx >= total) return;
    int c = (int)(idx % cpad);
    size_t t = idx / cpad;
    int o = (int)(t % DH);
    int k = (int)(t / DH);
    float v = (c < C) ? w[((size_t)o * C + c) * KW + k] : 0.0f;
    __nv_bfloat16 hi = __float2bfloat16(v);
    __nv_bfloat16 lo = __float2bfloat16(v - __bfloat162float(hi));
    wh[idx] = hi; wl[idx] = lo;
}

// ---------------------------------------------------------------------------
// Conv-GEMM via mma.sync. 256 threads = 8 warps: warp grid 4(m32) x 2(n64).
// ---------------------------------------------------------------------------
__global__ __launch_bounds__(256, 1)
void conv_mma_kernel(
    const __nv_bfloat16* __restrict__ Ah, const __nv_bfloat16* __restrict__ Al,
    int cpad, int nChunks,
    const __nv_bfloat16* __restrict__ Wh, const __nv_bfloat16* __restrict__ Wl,
    const unsigned* __restrict__ maskbits,
    const float* __restrict__ bias, const float* __restrict__ gamma,
    const float* __restrict__ beta, const float* __restrict__ mean,
    const float* __restrict__ var,
    int outFp32, float* __restrict__ outF,
    __nv_bfloat16* __restrict__ outH, __nv_bfloat16* __restrict__ outL)
{
    extern __shared__ __align__(128) char smem[];
    const uint32_t sA = smem_u32(smem);
    const uint32_t sB = sA + SM_B;

    const int tid  = threadIdx.x;
    const int wid  = tid >> 5;
    const int lane = tid & 31;
    const int mw   = wid & 3;     // m warp: 32 rows each
    const int nw   = wid >> 2;    // n warp: 64 cols each
    const int i0   = blockIdx.x * 128;
    const int o0   = blockIdx.y * 128;

    float acc[2][8][4];
#pragma unroll
    for (int tm = 0; tm < 2; ++tm)
#pragma unroll
        for (int n8 = 0; n8 < 8; ++n8)
#pragma unroll
            for (int q = 0; q < 4; ++q) acc[tm][n8][q] = 0.0f;

    // per-thread segment-mask words: rows held by this thread's A fragments
    unsigned mrow[2][2];
#pragma unroll
    for (int tm = 0; tm < 2; ++tm)
#pragma unroll
        for (int h = 0; h < 2; ++h)
            mrow[tm][h] = maskbits[i0 + mw * 32 + tm * 16 + h * 8 + (lane >> 2)];

    // ---- B register prefetch (32KB/stage: 8 x uint4 per thread) ----
    uint4 bpre[8];
    {
        const int cc = 0, k = 0;
#pragma unroll
        for (int j = 0; j < 8; ++j) {
            int g = tid + j * 256;
            int plane = g >> 10;
            int r = (g >> 3) & 127;
            int c = g & 7;
            const __nv_bfloat16* src =
                (plane ? Wl : Wh) + ((size_t)(k * DH + o0 + r)) * cpad + cc * 64 + c * 8;
            bpre[j] = *(const uint4*)src;
        }
    }

    const int T = nChunks * KW;
    for (int it = 0; it < T; ++it) {
        const int cc = it / KW;
        const int k  = it - cc * KW;
        const int stage = it & 1;

        __syncthreads();     // stage free, prev-cc A reads done
        // store prefetched B
#pragma unroll
        for (int j = 0; j < 8; ++j) {
            int g = tid + j * 256;
            int plane = g >> 10;
            int r = (g >> 3) & 127;
            int c = g & 7;
            *(uint4*)(smem + SM_B + stage * 32768 + plane * 16384 +
                      r * 128 + ((c ^ (r & 7)) << 4)) = bpre[j];
        }
        // A ext tile at chunk boundary
        if (k == 0) {
            for (int g = tid; g < 2176; g += 256) {
                int plane = g >= 1088;
                int rem = plane ? g - 1088 : g;
                int r = rem >> 3;
                int c = rem & 7;
                int tok = i0 - 4 + r;
                uint4 v = make_uint4(0, 0, 0, 0);
                if (tok >= 0 && tok < N_TOK)
                    v = *(const uint4*)((plane ? Al : Ah) +
                                        (size_t)tok * cpad + cc * 64 + c * 8);
                *(uint4*)(smem + plane * 17408 + r * 128 +
                          ((c ^ (r & 7)) << 4)) = v;
            }
        }
        __syncthreads();     // tiles visible

        // prefetch next iter's B (overlaps compute)
        if (it + 1 < T) {
            int nit = it + 1;
            int ncc = nit / KW;
            int nk  = nit - ncc * KW;
#pragma unroll
            for (int j = 0; j < 8; ++j) {
                int g = tid + j * 256;
                int plane = g >> 10;
                int r = (g >> 3) & 127;
                int c = g & 7;
                const __nv_bfloat16* src =
                    (plane ? Wl : Wh) + ((size_t)(nk * DH + o0 + r)) * cpad +
                    ncc * 64 + c * 8;
                bpre[j] = *(const uint4*)src;
            }
        }

        // tap mask predicates
        uint32_t z[2][2];
#pragma unroll
        for (int tm = 0; tm < 2; ++tm)
#pragma unroll
            for (int h = 0; h < 2; ++h) z[tm][h] = (mrow[tm][h] >> k) & 1u;

        // ---- compute: 4 k16-steps ----
#pragma unroll
        for (int ks = 0; ks < 4; ++ks) {
            uint32_t afr[2][2][4];   // [plane][tm][4]
#pragma unroll
            for (int p = 0; p < 2; ++p)
#pragma unroll
                for (int tm = 0; tm < 2; ++tm) {
                    int r = mw * 32 + tm * 16 + (lane & 15) + k;   // tap shift here
                    int c = ks * 2 + (lane >> 4);
                    uint32_t addr = sA + p * 17408 + r * 128 + ((c ^ (r & 7)) << 4);
                    ldm4(afr[p][tm], addr);
                }
            // segment mask on A fragments (rows lane>>2 and +8)
#pragma unroll
            for (int p = 0; p < 2; ++p)
#pragma unroll
                for (int tm = 0; tm < 2; ++tm) {
                    if (!z[tm][0]) { afr[p][tm][0] = 0u; afr[p][tm][2] = 0u; }
                    if (!z[tm][1]) { afr[p][tm][1] = 0u; afr[p][tm][3] = 0u; }
                }
            uint32_t bfr[2][4][4];   // [plane][nb(n16)][4]
#pragma unroll
            for (int p = 0; p < 2; ++p)
#pragma unroll
                for (int nb = 0; nb < 4; ++nb) {
                    int r = nw * 64 + nb * 16 + (((lane >> 4) & 1) << 3) + (lane & 7);
                    int c = ks * 2 + ((lane >> 3) & 1);
                    uint32_t addr = sB + stage * 32768 + p * 16384 +
                                    r * 128 + ((c ^ (r & 7)) << 4);
                    ldm4(bfr[p][nb], addr);
                }
#pragma unroll
            for (int tm = 0; tm < 2; ++tm)
#pragma unroll
                for (int nb = 0; nb < 4; ++nb)
#pragma unroll
                    for (int hf = 0; hf < 2; ++hf) {
                        int n8 = nb * 2 + hf;
                        mma16816(acc[tm][n8], afr[0][tm],
                                 bfr[0][nb][hf * 2], bfr[0][nb][hf * 2 + 1]); // Ah*Wh
                        mma16816(acc[tm][n8], afr[0][tm],
                                 bfr[1][nb][hf * 2], bfr[1][nb][hf * 2 + 1]); // Ah*Wl
                        mma16816(acc[tm][n8], afr[1][tm],
                                 bfr[0][nb][hf * 2], bfr[0][nb][hf * 2 + 1]); // Al*Wh
                    }
        }
    }

    // ---- epilogue: bias + ReLU + BN ----
#pragma unroll
    for (int tm = 0; tm < 2; ++tm) {
        int row = i0 + mw * 32 + tm * 16 + (lane >> 2);
#pragma unroll
        for (int n8 = 0; n8 < 8; ++n8) {
            int o = o0 + nw * 64 + n8 * 8 + (lane & 3) * 2;
            float s0 = gamma[o]     * rsqrtf(var[o]     + BN_EPS);
            float s1 = gamma[o + 1] * rsqrtf(var[o + 1] + BN_EPS);
            float h0 = beta[o]     - mean[o]     * s0;
            float h1 = beta[o + 1] - mean[o + 1] * s1;
            float bi0 = bias[o], bi1 = bias[o + 1];

            float v0 = fmaxf(acc[tm][n8][0] + bi0, 0.0f) * s0 + h0;
            float v1 = fmaxf(acc[tm][n8][1] + bi1, 0.0f) * s1 + h1;
            float v2 = fmaxf(acc[tm][n8][2] + bi0, 0.0f) * s0 + h0;
            float v3 = fmaxf(acc[tm][n8][3] + bi1, 0.0f) * s1 + h1;

            if (outFp32) {
                *(float2*)&outF[(size_t)row * DH + o]       = make_float2(v0, v1);
                *(float2*)&outF[(size_t)(row + 8) * DH + o] = make_float2(v2, v3);
            } else {
                __nv_bfloat16 a0 = __float2bfloat16(v0), a1 = __float2bfloat16(v1);
                __nv_bfloat16 a2 = __float2bfloat16(v2), a3 = __float2bfloat16(v3);
                __nv_bfloat16 l0 = __float2bfloat16(v0 - __bfloat162float(a0));
                __nv_bfloat16 l1 = __float2bfloat16(v1 - __bfloat162float(a1));
                __nv_bfloat16 l2 = __float2bfloat16(v2 - __bfloat162float(a2));
                __nv_bfloat16 l3 = __float2bfloat16(v3 - __bfloat162float(a3));
                unsigned hp0 = (unsigned)*(unsigned short*)&a0 |
                               ((unsigned)*(unsigned short*)&a1 << 16);
                unsigned lp0 = (unsigned)*(unsigned short*)&l0 |
                               ((unsigned)*(unsigned short*)&l1 << 16);
                unsigned hp1 = (unsigned)*(unsigned short*)&a2 |
                               ((unsigned)*(unsigned short*)&a3 << 16);
                unsigned lp1 = (unsigned)*(unsigned short*)&l2 |
                               ((unsigned)*(unsigned short*)&l3 << 16);
                *(unsigned*)&outH[(size_t)row * DH + o]       = hp0;
                *(unsigned*)&outL[(size_t)row * DH + o]       = lp0;
                *(unsigned*)&outH[(size_t)(row + 8) * DH + o] = hp1;
                *(unsigned*)&outL[(size_t)(row + 8) * DH + o] = lp1;
            }
        }
    }
}

// ---------------------------------------------------------------------------
__global__ void final_kernel(const float* __restrict__ h,
                             const float* __restrict__ wl,
                             const float* __restrict__ bl,
                             float* __restrict__ out)
{
    int gwarp = (blockIdx.x * blockDim.x + threadIdx.x) >> 5;
    int lane  = threadIdx.x & 31;
    if (gwarp >= N_TOK) return;

    const float4* hv = (const float4*)(h + (size_t)gwarp * DH);
    const float4* w0 = (const float4*)(wl);
    const float4* w1 = (const float4*)(wl + DH);

    float s0 = 0.0f, s1 = 0.0f;
    for (int j = lane; j < DH / 4; j += 32) {
        float4 a  = hv[j];
        float4 c0 = w0[j];
        float4 c1 = w1[j];
        s0 += a.x * c0.x + a.y * c0.y + a.z * c0.z + a.w * c0.w;
        s1 += a.x * c1.x + a.y * c1.y + a.z * c1.z + a.w * c1.w;
    }
#pragma unroll
    for (int off = 16; off > 0; off >>= 1) {
        s0 += __shfl_xor_sync(0xFFFFFFFFu, s0, off);
        s1 += __shfl_xor_sync(0xFFFFFFFFu, s1, off);
    }
    if (lane == 0) {
        float z0 = s0 + bl[0];
        float z1 = s1 + bl[1];
        float mx = fmaxf(z0, z1);
        float e0 = expf(z0 - mx);
        float e1 = expf(z1 - mx);
        float inv = 1.0f / (e0 + e1);
        out[(size_t)gwarp * 2 + 0] = z0;
        out[(size_t)gwarp * 2 + 1] = z1;
        out[(size_t)2 * N_TOK + (size_t)gwarp * 2 + 0] = e0 * inv;
        out[(size_t)2 * N_TOK + (size_t)gwarp * 2 + 1] = e1 * inv;
    }
}

// ---------------------------------------------------------------------------
extern "C" void kernel_launch(void* const* d_in, const int* in_sizes, int n_in,
                              void* d_out, int out_size) {
    const float* x   = (const float*)d_in[0];
    const int*   seg = (const int*)d_in[1];      // int32 (JAX x64 disabled)
    const float* w1  = (const float*)d_in[2];
    const float* b1  = (const float*)d_in[3];
    const float* g1  = (const float*)d_in[4];
    const float* be1 = (const float*)d_in[5];
    const float* m1  = (const float*)d_in[6];
    const float* v1  = (const float*)d_in[7];
    const float* w2  = (const float*)d_in[8];
    const float* b2  = (const float*)d_in[9];
    const float* g2  = (const float*)d_in[10];
    const float* be2 = (const float*)d_in[11];
    const float* m2  = (const float*)d_in[12];
    const float* v2  = (const float*)d_in[13];
    const float* wl  = (const float*)d_in[14];
    const float* bl  = (const float*)d_in[15];
    float* out = (float*)d_out;

    __nv_bfloat16 *xh, *xl, *w1h, *w1l, *w2h, *w2l, *h1h, *h1l;
    float* h2;
    unsigned* mask;
    cudaGetSymbolAddress((void**)&xh,  g_xh);
    cudaGetSymbolAddress((void**)&xl,  g_xl);
    cudaGetSymbolAddress((void**)&w1h, g_w1h);
    cudaGetSymbolAddress((void**)&w1l, g_w1l);
    cudaGetSymbolAddress((void**)&w2h, g_w2h);
    cudaGetSymbolAddress((void**)&w2l, g_w2l);
    cudaGetSymbolAddress((void**)&h1h, g_h1h);
    cudaGetSymbolAddress((void**)&h1l, g_h1l);
    cudaGetSymbolAddress((void**)&h2,  g_h2);
    cudaGetSymbolAddress((void**)&mask, g_mask);

    cudaFuncSetAttribute(conv_mma_kernel,
                         cudaFuncAttributeMaxDynamicSharedMemorySize, SMEM_TOTAL);

    mask_kernel<<<(N_TOK + 255) / 256, 256>>>(seg, mask);

    {
        size_t tx = (size_t)N_TOK * CP1;
        split_x_kernel<<<(unsigned)((tx + 255) / 256), 256>>>(x, xh, xl);
        size_t t1 = (size_t)KW * DH * CP1;
        split_w_kernel<<<(unsigned)((t1 + 255) / 256), 256>>>(w1, w1h, w1l, DIN, CP1);
        size_t t2 = (size_t)KW * DH * DH;
        split_w_kernel<<<(unsigned)((t2 + 255) / 256), 256>>>(w2, w2h, w2l, DH, DH);
    }

    dim3 grid(N_TOK / 128, DH / 128);   // m fastest -> B panel hot in L2
    conv_mma_kernel<<<grid, 256, SMEM_TOTAL>>>(
        xh, xl, CP1, CP1 / 64, w1h, w1l, mask,
        b1, g1, be1, m1, v1, 0, nullptr, h1h, h1l);
    conv_mma_kernel<<<grid, 256, SMEM_TOTAL>>>(
        h1h, h1l, DH, DH / 64, w2h, w2l, mask,
        b2, g2, be2, m2, v2, 1, h2, nullptr, nullptr);

    final_kernel<<<(N_TOK * 32 + 127) / 128, 128>>>(h2, wl, bl, out);
}

// round 12
// speedup vs baseline: 3.6564x; 1.1338x over previous
#include <cuda_runtime.h>
#include <cuda_bf16.h>
#include <cstdint>
#include <math.h>

// ---------------------------------------------------------------------------
// PainHead via warp-level bf16 mma.sync (m16n8k16) split-GEMM.
// D = Ah*Wh + Ah*Wl + Al*Wh with fp32 accumulators (bf16x3 scheme).
// CTA tile: 128 tokens x 128 outputs; K-loop: 64-ch chunks x 9 taps.
// Round 10: (1) coalesced smem-transpose weight split; (2) cp.async staging
// for A/B tiles + __launch_bounds__(256,2) for 2 CTAs/SM latency hiding.
// ---------------------------------------------------------------------------

#define N_TOK 8192
#define DIN   600
#define CP1   640
#define DH    2048
#define KW    9
#define BN_EPS 1e-5f

// ---------------- device scratch ----------------
__device__ __nv_bfloat16 g_xh[(size_t)N_TOK * CP1];
__device__ __nv_bfloat16 g_xl[(size_t)N_TOK * CP1];
__device__ __nv_bfloat16 g_w1h[(size_t)KW * DH * CP1];
__device__ __nv_bfloat16 g_w1l[(size_t)KW * DH * CP1];
__device__ __nv_bfloat16 g_w2h[(size_t)KW * DH * DH];
__device__ __nv_bfloat16 g_w2l[(size_t)KW * DH * DH];
__device__ __nv_bfloat16 g_h1h[(size_t)N_TOK * DH];
__device__ __nv_bfloat16 g_h1l[(size_t)N_TOK * DH];
__device__ float         g_h2[(size_t)N_TOK * DH];
__device__ unsigned      g_mask[N_TOK];

// ---------------- helpers ----------------
__device__ __forceinline__ uint32_t smem_u32(const void* p) {
    uint32_t a;
    asm("{ .reg .u64 t; cvta.to.shared.u64 t, %1; cvt.u32.u64 %0, t; }"
        : "=r"(a) : "l"(p));
    return a;
}
__device__ __forceinline__ void ldm4(uint32_t* r, uint32_t addr) {
    asm volatile("ldmatrix.sync.aligned.m8n8.x4.shared.b16 {%0,%1,%2,%3}, [%4];"
                 : "=r"(r[0]), "=r"(r[1]), "=r"(r[2]), "=r"(r[3]) : "r"(addr));
}
__device__ __forceinline__ void mma16816(float* d, const uint32_t* a,
                                         uint32_t b0, uint32_t b1) {
    asm volatile(
        "mma.sync.aligned.m16n8k16.row.col.f32.bf16.bf16.f32 "
        "{%0,%1,%2,%3}, {%4,%5,%6,%7}, {%8,%9}, {%0,%1,%2,%3};"
        : "+f"(d[0]), "+f"(d[1]), "+f"(d[2]), "+f"(d[3])
        : "r"(a[0]), "r"(a[1]), "r"(a[2]), "r"(a[3]), "r"(b0), "r"(b1));
}
__device__ __forceinline__ void cp_async16(uint32_t smem_addr, const void* gptr) {
    asm volatile("cp.async.cg.shared.global [%0], [%1], 16;"
                 :: "r"(smem_addr), "l"(gptr));
}
__device__ __forceinline__ void cp_commit() {
    asm volatile("cp.async.commit_group;");
}
__device__ __forceinline__ void cp_wait0() {
    asm volatile("cp.async.wait_group 0;");
}
__device__ __forceinline__ void cp_wait1() {
    asm volatile("cp.async.wait_group 1;");
}

// ---------------- smem layout ----------------
// A ext: 2 planes x 136 rows x 128B = 34816
// B:     2 stages x 2 planes x 128 rows x 128B = 65536
#define SM_A      0
#define SM_B      34816
#define SMEM_TOTAL 100352

// ---------------------------------------------------------------------------
__global__ void mask_kernel(const int* __restrict__ seg, unsigned* __restrict__ bits) {
    int i = blockIdx.x * blockDim.x + threadIdx.x;
    if (i >= N_TOK) return;
    int s = seg[i];
    unsigned b = 0;
#pragma unroll
    for (int k = 0; k < KW; ++k) {
        int j = i + k - KW / 2;
        if (j >= 0 && j < N_TOK && seg[j] == s) b |= (1u << k);
    }
    bits[i] = b;
}

__global__ void split_x_kernel(const float* __restrict__ x,
                               __nv_bfloat16* __restrict__ xh,
                               __nv_bfloat16* __restrict__ xl) {
    size_t idx = (size_t)blockIdx.x * blockDim.x + threadIdx.x;
    if (idx >= (size_t)N_TOK * CP1) return;
    int c = (int)(idx % CP1);
    int r = (int)(idx / CP1);
    float v = (c < DIN) ? x[(size_t)r * DIN + c] : 0.0f;
    __nv_bfloat16 hi = __float2bfloat16(v);
    __nv_bfloat16 lo = __float2bfloat16(v - __bfloat162float(hi));
    xh[idx] = hi; xl[idx] = lo;
}

// Coalesced weight split: one block per output row o. Reads w[o][*][*]
// contiguously into smem, writes wt[k][o][*] hi/lo contiguously.
__global__ void wsplit_kernel(const float* __restrict__ w,
                              __nv_bfloat16* __restrict__ wh,
                              __nv_bfloat16* __restrict__ wl,
                              int C, int cpad) {
    extern __shared__ float sw[];
    const int o   = blockIdx.x;
    const int tid = threadIdx.x;
    const float* src = w + (size_t)o * C * KW;
    const int total = C * KW;
    for (int i = tid; i < total; i += blockDim.x) sw[i] = src[i];
    __syncthreads();
#pragma unroll
    for (int k = 0; k < KW; ++k) {
        size_t base = ((size_t)k * DH + o) * cpad;
        for (int c = tid; c < cpad; c += blockDim.x) {
            float v = (c < C) ? sw[c * KW + k] : 0.0f;
            __nv_bfloat16 hi = __float2bfloat16(v);
            __nv_bfloat16 lo = __float2bfloat16(v - __bfloat162float(hi));
            wh[base + c] = hi;
            wl[base + c] = lo;
        }
    }
}

// ---------------------------------------------------------------------------
// Conv-GEMM via mma.sync. 256 threads = 8 warps: warp grid 4(m32) x 2(n64).
// cp.async 2-stage B pipeline; A-ext filled per 64-ch chunk.
// ---------------------------------------------------------------------------
__global__ __launch_bounds__(256, 2)
void conv_mma_kernel(
    const __nv_bfloat16* __restrict__ Ah, const __nv_bfloat16* __restrict__ Al,
    int cpad, int nChunks,
    const __nv_bfloat16* __restrict__ Wh, const __nv_bfloat16* __restrict__ Wl,
    const unsigned* __restrict__ maskbits,
    const float* __restrict__ bias, const float* __restrict__ gamma,
    const float* __restrict__ beta, const float* __restrict__ mean,
    const float* __restrict__ var,
    int outFp32, float* __restrict__ outF,
    __nv_bfloat16* __restrict__ outH, __nv_bfloat16* __restrict__ outL)
{
    extern __shared__ __align__(128) char smem[];
    const uint32_t sA = smem_u32(smem);
    const uint32_t sB = sA + SM_B;

    const int tid  = threadIdx.x;
    const int wid  = tid >> 5;
    const int lane = tid & 31;
    const int mw   = wid & 3;     // m warp: 32 rows each
    const int nw   = wid >> 2;    // n warp: 64 cols each
    const int i0   = blockIdx.x * 128;
    const int o0   = blockIdx.y * 128;

    float acc[2][8][4];
#pragma unroll
    for (int tm = 0; tm < 2; ++tm)
#pragma unroll
        for (int n8 = 0; n8 < 8; ++n8)
#pragma unroll
            for (int q = 0; q < 4; ++q) acc[tm][n8][q] = 0.0f;

    unsigned mrow[2][2];
#pragma unroll
    for (int tm = 0; tm < 2; ++tm)
#pragma unroll
        for (int h = 0; h < 2; ++h)
            mrow[tm][h] = maskbits[i0 + mw * 32 + tm * 16 + h * 8 + (lane >> 2)];

    // prologue: issue B(0) into stage 0
    {
#pragma unroll
        for (int j = 0; j < 8; ++j) {
            int g = tid + j * 256;
            int plane = g >> 10;
            int r = (g >> 3) & 127;
            int c = g & 7;
            const __nv_bfloat16* src =
                (plane ? Wl : Wh) + ((size_t)(o0 + r)) * cpad + c * 8;
            uint32_t dst = sB + plane * 16384 + r * 128 + ((c ^ (r & 7)) << 4);
            cp_async16(dst, src);
        }
        cp_commit();
    }

    const int T = nChunks * KW;
    for (int it = 0; it < T; ++it) {
        const int cc = it / KW;
        const int k  = it - cc * KW;
        const int stage = it & 1;

        cp_wait0();          // B(it) complete (own groups)
        __syncthreads();     // visibility; stage^1 and A buffer now free

        if (k == 0) {
            // fill A-ext for chunk cc (buffer free after the barrier above)
            for (int g = tid; g < 2176; g += 256) {
                int plane = g >= 1088;
                int rem = plane ? g - 1088 : g;
                int r = rem >> 3;
                int c = rem & 7;
                int tok = i0 - 4 + r;
                uint32_t off = plane * 17408 + r * 128 + ((c ^ (r & 7)) << 4);
                if (tok >= 0 && tok < N_TOK) {
                    cp_async16(sA + off, (plane ? Al : Ah) +
                               (size_t)tok * cpad + cc * 64 + c * 8);
                } else {
                    *(uint4*)(smem + off) = make_uint4(0, 0, 0, 0);
                }
            }
            cp_commit();     // A group (older than B-next below)
        }
        if (it + 1 < T) {
            int ncc = (it + 1) / KW;
            int nk  = (it + 1) - ncc * KW;
#pragma unroll
            for (int j = 0; j < 8; ++j) {
                int g = tid + j * 256;
                int plane = g >> 10;
                int r = (g >> 3) & 127;
                int c = g & 7;
                const __nv_bfloat16* src =
                    (plane ? Wl : Wh) + ((size_t)(nk * DH + o0 + r)) * cpad +
                    ncc * 64 + c * 8;
                uint32_t dst = sB + (stage ^ 1) * 32768 + plane * 16384 +
                               r * 128 + ((c ^ (r & 7)) << 4);
                cp_async16(dst, src);
            }
            cp_commit();     // B(it+1) group stays in flight during compute
        }
        if (k == 0) {
            cp_wait1();      // drain A (B(it+1) may remain pending)
            __syncthreads(); // A visible to all warps
        }

        // tap mask predicates
        uint32_t z[2][2];
#pragma unroll
        for (int tm = 0; tm < 2; ++tm)
#pragma unroll
            for (int h = 0; h < 2; ++h) z[tm][h] = (mrow[tm][h] >> k) & 1u;

        // ---- compute: 4 k16-steps ----
#pragma unroll
        for (int ks = 0; ks < 4; ++ks) {
            uint32_t afr[2][2][4];   // [plane][tm][4]
#pragma unroll
            for (int p = 0; p < 2; ++p)
#pragma unroll
                for (int tm = 0; tm < 2; ++tm) {
                    int r = mw * 32 + tm * 16 + (lane & 15) + k;   // tap shift
                    int c = ks * 2 + (lane >> 4);
                    uint32_t addr = sA + p * 17408 + r * 128 + ((c ^ (r & 7)) << 4);
                    ldm4(afr[p][tm], addr);
                }
#pragma unroll
            for (int p = 0; p < 2; ++p)
#pragma unroll
                for (int tm = 0; tm < 2; ++tm) {
                    if (!z[tm][0]) { afr[p][tm][0] = 0u; afr[p][tm][2] = 0u; }
                    if (!z[tm][1]) { afr[p][tm][1] = 0u; afr[p][tm][3] = 0u; }
                }
            uint32_t bfr[2][4][4];   // [plane][nb(n16)][4]
#pragma unroll
            for (int p = 0; p < 2; ++p)
#pragma unroll
                for (int nb = 0; nb < 4; ++nb) {
                    int r = nw * 64 + nb * 16 + (((lane >> 4) & 1) << 3) + (lane & 7);
                    int c = ks * 2 + ((lane >> 3) & 1);
                    uint32_t addr = sB + stage * 32768 + p * 16384 +
                                    r * 128 + ((c ^ (r & 7)) << 4);
                    ldm4(bfr[p][nb], addr);
                }
#pragma unroll
            for (int tm = 0; tm < 2; ++tm)
#pragma unroll
                for (int nb = 0; nb < 4; ++nb)
#pragma unroll
                    for (int hf = 0; hf < 2; ++hf) {
                        int n8 = nb * 2 + hf;
                        mma16816(acc[tm][n8], afr[0][tm],
                                 bfr[0][nb][hf * 2], bfr[0][nb][hf * 2 + 1]); // Ah*Wh
                        mma16816(acc[tm][n8], afr[0][tm],
                                 bfr[1][nb][hf * 2], bfr[1][nb][hf * 2 + 1]); // Ah*Wl
                        mma16816(acc[tm][n8], afr[1][tm],
                                 bfr[0][nb][hf * 2], bfr[0][nb][hf * 2 + 1]); // Al*Wh
                    }
        }
    }

    // ---- epilogue: bias + ReLU + BN ----
#pragma unroll
    for (int tm = 0; tm < 2; ++tm) {
        int row = i0 + mw * 32 + tm * 16 + (lane >> 2);
#pragma unroll
        for (int n8 = 0; n8 < 8; ++n8) {
            int o = o0 + nw * 64 + n8 * 8 + (lane & 3) * 2;
            float s0 = gamma[o]     * rsqrtf(var[o]     + BN_EPS);
            float s1 = gamma[o + 1] * rsqrtf(var[o + 1] + BN_EPS);
            float h0 = beta[o]     - mean[o]     * s0;
            float h1 = beta[o + 1] - mean[o + 1] * s1;
            float bi0 = bias[o], bi1 = bias[o + 1];

            float v0 = fmaxf(acc[tm][n8][0] + bi0, 0.0f) * s0 + h0;
            float v1 = fmaxf(acc[tm][n8][1] + bi1, 0.0f) * s1 + h1;
            float v2 = fmaxf(acc[tm][n8][2] + bi0, 0.0f) * s0 + h0;
            float v3 = fmaxf(acc[tm][n8][3] + bi1, 0.0f) * s1 + h1;

            if (outFp32) {
                *(float2*)&outF[(size_t)row * DH + o]       = make_float2(v0, v1);
                *(float2*)&outF[(size_t)(row + 8) * DH + o] = make_float2(v2, v3);
            } else {
                __nv_bfloat16 a0 = __float2bfloat16(v0), a1 = __float2bfloat16(v1);
                __nv_bfloat16 a2 = __float2bfloat16(v2), a3 = __float2bfloat16(v3);
                __nv_bfloat16 l0 = __float2bfloat16(v0 - __bfloat162float(a0));
                __nv_bfloat16 l1 = __float2bfloat16(v1 - __bfloat162float(a1));
                __nv_bfloat16 l2 = __float2bfloat16(v2 - __bfloat162float(a2));
                __nv_bfloat16 l3 = __float2bfloat16(v3 - __bfloat162float(a3));
                unsigned hp0 = (unsigned)*(unsigned short*)&a0 |
                               ((unsigned)*(unsigned short*)&a1 << 16);
                unsigned lp0 = (unsigned)*(unsigned short*)&l0 |
                               ((unsigned)*(unsigned short*)&l1 << 16);
                unsigned hp1 = (unsigned)*(unsigned short*)&a2 |
                               ((unsigned)*(unsigned short*)&a3 << 16);
                unsigned lp1 = (unsigned)*(unsigned short*)&l2 |
                               ((unsigned)*(unsigned short*)&l3 << 16);
                *(unsigned*)&outH[(size_t)row * DH + o]       = hp0;
                *(unsigned*)&outL[(size_t)row * DH + o]       = lp0;
                *(unsigned*)&outH[(size_t)(row + 8) * DH + o] = hp1;
                *(unsigned*)&outL[(size_t)(row + 8) * DH + o] = lp1;
            }
        }
    }
}

// ---------------------------------------------------------------------------
__global__ void final_kernel(const float* __restrict__ h,
                             const float* __restrict__ wl,
                             const float* __restrict__ bl,
                             float* __restrict__ out)
{
    int gwarp = (blockIdx.x * blockDim.x + threadIdx.x) >> 5;
    int lane  = threadIdx.x & 31;
    if (gwarp >= N_TOK) return;

    const float4* hv = (const float4*)(h + (size_t)gwarp * DH);
    const float4* w0 = (const float4*)(wl);
    const float4* w1 = (const float4*)(wl + DH);

    float s0 = 0.0f, s1 = 0.0f;
    for (int j = lane; j < DH / 4; j += 32) {
        float4 a  = hv[j];
        float4 c0 = w0[j];
        float4 c1 = w1[j];
        s0 += a.x * c0.x + a.y * c0.y + a.z * c0.z + a.w * c0.w;
        s1 += a.x * c1.x + a.y * c1.y + a.z * c1.z + a.w * c1.w;
    }
#pragma unroll
    for (int off = 16; off > 0; off >>= 1) {
        s0 += __shfl_xor_sync(0xFFFFFFFFu, s0, off);
        s1 += __shfl_xor_sync(0xFFFFFFFFu, s1, off);
    }
    if (lane == 0) {
        float z0 = s0 + bl[0];
        float z1 = s1 + bl[1];
        float mx = fmaxf(z0, z1);
        float e0 = expf(z0 - mx);
        float e1 = expf(z1 - mx);
        float inv = 1.0f / (e0 + e1);
        out[(size_t)gwarp * 2 + 0] = z0;
        out[(size_t)gwarp * 2 + 1] = z1;
        out[(size_t)2 * N_TOK + (size_t)gwarp * 2 + 0] = e0 * inv;
        out[(size_t)2 * N_TOK + (size_t)gwarp * 2 + 1] = e1 * inv;
    }
}

// ---------------------------------------------------------------------------
extern "C" void kernel_launch(void* const* d_in, const int* in_sizes, int n_in,
                              void* d_out, int out_size) {
    const float* x   = (const float*)d_in[0];
    const int*   seg = (const int*)d_in[1];      // int32 (JAX x64 disabled)
    const float* w1  = (const float*)d_in[2];
    const float* b1  = (const float*)d_in[3];
    const float* g1  = (const float*)d_in[4];
    const float* be1 = (const float*)d_in[5];
    const float* m1  = (const float*)d_in[6];
    const float* v1  = (const float*)d_in[7];
    const float* w2  = (const float*)d_in[8];
    const float* b2  = (const float*)d_in[9];
    const float* g2  = (const float*)d_in[10];
    const float* be2 = (const float*)d_in[11];
    const float* m2  = (const float*)d_in[12];
    const float* v2  = (const float*)d_in[13];
    const float* wl  = (const float*)d_in[14];
    const float* bl  = (const float*)d_in[15];
    float* out = (float*)d_out;

    __nv_bfloat16 *xh, *xl, *w1h, *w1l, *w2h, *w2l, *h1h, *h1l;
    float* h2;
    unsigned* mask;
    cudaGetSymbolAddress((void**)&xh,  g_xh);
    cudaGetSymbolAddress((void**)&xl,  g_xl);
    cudaGetSymbolAddress((void**)&w1h, g_w1h);
    cudaGetSymbolAddress((void**)&w1l, g_w1l);
    cudaGetSymbolAddress((void**)&w2h, g_w2h);
    cudaGetSymbolAddress((void**)&w2l, g_w2l);
    cudaGetSymbolAddress((void**)&h1h, g_h1h);
    cudaGetSymbolAddress((void**)&h1l, g_h1l);
    cudaGetSymbolAddress((void**)&h2,  g_h2);
    cudaGetSymbolAddress((void**)&mask, g_mask);

    cudaFuncSetAttribute(conv_mma_kernel,
                         cudaFuncAttributeMaxDynamicSharedMemorySize, SMEM_TOTAL);
    cudaFuncSetAttribute(wsplit_kernel,
                         cudaFuncAttributeMaxDynamicSharedMemorySize,
                         DH * KW * (int)sizeof(float));

    mask_kernel<<<(N_TOK + 255) / 256, 256>>>(seg, mask);

    {
        size_t tx = (size_t)N_TOK * CP1;
        split_x_kernel<<<(unsigned)((tx + 255) / 256), 256>>>(x, xh, xl);
        wsplit_kernel<<<DH, 256, DIN * KW * sizeof(float)>>>(w1, w1h, w1l, DIN, CP1);
        wsplit_kernel<<<DH, 256, DH * KW * sizeof(float)>>>(w2, w2h, w2l, DH, DH);
    }

    dim3 grid(N_TOK / 128, DH / 128);   // m fastest -> B panel hot in L2
    conv_mma_kernel<<<grid, 256, SMEM_TOTAL>>>(
        xh, xl, CP1, CP1 / 64, w1h, w1l, mask,
        b1, g1, be1, m1, v1, 0, nullptr, h1h, h1l);
    conv_mma_kernel<<<grid, 256, SMEM_TOTAL>>>(
        h1h, h1l, DH, DH / 64, w2h, w2l, mask,
        b2, g2, be2, m2, v2, 1, h2, nullptr, nullptr);

    final_kernel<<<(N_TOK * 32 + 127) / 128, 128>>>(h2, wl, bl, out);
}

// round 13
// speedup vs baseline: 3.9363x; 1.0765x over previous
#include <cuda_runtime.h>
#include <cuda_bf16.h>
#include <cstdint>
#include <math.h>

// ---------------------------------------------------------------------------
// PainHead via warp-level bf16 mma.sync (m16n8k16) split-GEMM.
// D = Ah*Wh + Ah*Wl + Al*Wh with fp32 accumulators (bf16x3 scheme).
// CTA tile: 128 tokens x 128 outputs; K-loop: 64-ch chunks x 9 taps.
// Round 12: 4 warps x 64x64 warp tiles (LDS per MMA -33%; smem was the
// binding pipe), product-outermost MMA order, vectorized wsplit.
// ---------------------------------------------------------------------------

#define N_TOK 8192
#define DIN   600
#define CP1   640
#define DH    2048
#define KW    9
#define BN_EPS 1e-5f

// ---------------- device scratch ----------------
__device__ __nv_bfloat16 g_xh[(size_t)N_TOK * CP1];
__device__ __nv_bfloat16 g_xl[(size_t)N_TOK * CP1];
__device__ __nv_bfloat16 g_w1h[(size_t)KW * DH * CP1];
__device__ __nv_bfloat16 g_w1l[(size_t)KW * DH * CP1];
__device__ __nv_bfloat16 g_w2h[(size_t)KW * DH * DH];
__device__ __nv_bfloat16 g_w2l[(size_t)KW * DH * DH];
__device__ __nv_bfloat16 g_h1h[(size_t)N_TOK * DH];
__device__ __nv_bfloat16 g_h1l[(size_t)N_TOK * DH];
__device__ float         g_h2[(size_t)N_TOK * DH];
__device__ unsigned      g_mask[N_TOK];

// ---------------- helpers ----------------
__device__ __forceinline__ uint32_t smem_u32(const void* p) {
    uint32_t a;
    asm("{ .reg .u64 t; cvta.to.shared.u64 t, %1; cvt.u32.u64 %0, t; }"
        : "=r"(a) : "l"(p));
    return a;
}
__device__ __forceinline__ void ldm4(uint32_t* r, uint32_t addr) {
    asm volatile("ldmatrix.sync.aligned.m8n8.x4.shared.b16 {%0,%1,%2,%3}, [%4];"
                 : "=r"(r[0]), "=r"(r[1]), "=r"(r[2]), "=r"(r[3]) : "r"(addr));
}
__device__ __forceinline__ void mma16816(float* d, const uint32_t* a,
                                         uint32_t b0, uint32_t b1) {
    asm volatile(
        "mma.sync.aligned.m16n8k16.row.col.f32.bf16.bf16.f32 "
        "{%0,%1,%2,%3}, {%4,%5,%6,%7}, {%8,%9}, {%0,%1,%2,%3};"
        : "+f"(d[0]), "+f"(d[1]), "+f"(d[2]), "+f"(d[3])
        : "r"(a[0]), "r"(a[1]), "r"(a[2]), "r"(a[3]), "r"(b0), "r"(b1));
}
__device__ __forceinline__ void cp_async16(uint32_t smem_addr, const void* gptr) {
    asm volatile("cp.async.cg.shared.global [%0], [%1], 16;"
                 :: "r"(smem_addr), "l"(gptr));
}
__device__ __forceinline__ void cp_commit() {
    asm volatile("cp.async.commit_group;");
}
__device__ __forceinline__ void cp_wait0() {
    asm volatile("cp.async.wait_group 0;");
}
__device__ __forceinline__ void cp_wait1() {
    asm volatile("cp.async.wait_group 1;");
}

// ---------------- smem layout ----------------
// A ext: 2 planes x 136 rows x 128B = 34816
// B:     2 stages x 2 planes x 128 rows x 128B = 65536
#define SM_A      0
#define SM_B      34816
#define SMEM_TOTAL 100352

// ---------------------------------------------------------------------------
__global__ void mask_kernel(const int* __restrict__ seg, unsigned* __restrict__ bits) {
    int i = blockIdx.x * blockDim.x + threadIdx.x;
    if (i >= N_TOK) return;
    int s = seg[i];
    unsigned b = 0;
#pragma unroll
    for (int k = 0; k < KW; ++k) {
        int j = i + k - KW / 2;
        if (j >= 0 && j < N_TOK && seg[j] == s) b |= (1u << k);
    }
    bits[i] = b;
}

__global__ void split_x_kernel(const float* __restrict__ x,
                               __nv_bfloat16* __restrict__ xh,
                               __nv_bfloat16* __restrict__ xl) {
    size_t idx = (size_t)blockIdx.x * blockDim.x + threadIdx.x;
    if (idx >= (size_t)N_TOK * CP1) return;
    int c = (int)(idx % CP1);
    int r = (int)(idx / CP1);
    float v = (c < DIN) ? x[(size_t)r * DIN + c] : 0.0f;
    __nv_bfloat16 hi = __float2bfloat16(v);
    __nv_bfloat16 lo = __float2bfloat16(v - __bfloat162float(hi));
    xh[idx] = hi; xl[idx] = lo;
}

// Coalesced weight split, vectorized: one block (512 thr) per output row o.
// float4 loads into smem; packed 2xbf16 32-bit stores per plane.
__global__ void wsplit_kernel(const float* __restrict__ w,
                              __nv_bfloat16* __restrict__ wh,
                              __nv_bfloat16* __restrict__ wl,
                              int C, int cpad) {
    extern __shared__ float sw[];
    const int o   = blockIdx.x;
    const int tid = threadIdx.x;
    const int nt  = blockDim.x;
    const float4* src4 = (const float4*)(w + (size_t)o * C * KW);
    const int total4 = (C * KW) / 4;          // 5400/4, 18432/4 both exact
    for (int i = tid; i < total4; i += nt) ((float4*)sw)[i] = src4[i];
    __syncthreads();
#pragma unroll
    for (int k = 0; k < KW; ++k) {
        size_t base = ((size_t)k * DH + o) * cpad;
        for (int c2 = tid; c2 < cpad / 2; c2 += nt) {
            int c = c2 * 2;
            float v0 = (c     < C) ? sw[c * KW + k]       : 0.0f;
            float v1 = (c + 1 < C) ? sw[(c + 1) * KW + k] : 0.0f;
            __nv_bfloat16 h0 = __float2bfloat16(v0);
            __nv_bfloat16 h1 = __float2bfloat16(v1);
            __nv_bfloat16 l0 = __float2bfloat16(v0 - __bfloat162float(h0));
            __nv_bfloat16 l1 = __float2bfloat16(v1 - __bfloat162float(h1));
            unsigned hp = (unsigned)*(unsigned short*)&h0 |
                          ((unsigned)*(unsigned short*)&h1 << 16);
            unsigned lp = (unsigned)*(unsigned short*)&l0 |
                          ((unsigned)*(unsigned short*)&l1 << 16);
            *(unsigned*)&wh[base + c] = hp;
            *(unsigned*)&wl[base + c] = lp;
        }
    }
}

// ---------------------------------------------------------------------------
// Conv-GEMM via mma.sync. 128 threads = 4 warps: warp grid 2(m64) x 2(n64).
// cp.async 2-stage B pipeline; A-ext filled per 64-ch chunk.
// ---------------------------------------------------------------------------
__global__ __launch_bounds__(128)
void conv_mma_kernel(
    const __nv_bfloat16* __restrict__ Ah, const __nv_bfloat16* __restrict__ Al,
    int cpad, int nChunks,
    const __nv_bfloat16* __restrict__ Wh, const __nv_bfloat16* __restrict__ Wl,
    const unsigned* __restrict__ maskbits,
    const float* __restrict__ bias, const float* __restrict__ gamma,
    const float* __restrict__ beta, const float* __restrict__ mean,
    const float* __restrict__ var,
    int outFp32, float* __restrict__ outF,
    __nv_bfloat16* __restrict__ outH, __nv_bfloat16* __restrict__ outL)
{
    extern __shared__ __align__(128) char smem[];
    const uint32_t sA = smem_u32(smem);
    const uint32_t sB = sA + SM_B;

    const int tid  = threadIdx.x;
    const int wid  = tid >> 5;
    const int lane = tid & 31;
    const int mw   = wid & 1;     // m warp: 64 rows each
    const int nw   = wid >> 1;    // n warp: 64 cols each
    const int i0   = blockIdx.x * 128;
    const int o0   = blockIdx.y * 128;

    float acc[4][8][4];
#pragma unroll
    for (int tm = 0; tm < 4; ++tm)
#pragma unroll
        for (int n8 = 0; n8 < 8; ++n8)
#pragma unroll
            for (int q = 0; q < 4; ++q) acc[tm][n8][q] = 0.0f;

    unsigned mrow[4][2];
#pragma unroll
    for (int tm = 0; tm < 4; ++tm)
#pragma unroll
        for (int h = 0; h < 2; ++h)
            mrow[tm][h] = maskbits[i0 + mw * 64 + tm * 16 + h * 8 + (lane >> 2)];

    // prologue: issue B(0) into stage 0
    {
#pragma unroll
        for (int j = 0; j < 16; ++j) {
            int g = tid + j * 128;
            int plane = g >> 10;
            int r = (g >> 3) & 127;
            int c = g & 7;
            const __nv_bfloat16* src =
                (plane ? Wl : Wh) + ((size_t)(o0 + r)) * cpad + c * 8;
            uint32_t dst = sB + plane * 16384 + r * 128 + ((c ^ (r & 7)) << 4);
            cp_async16(dst, src);
        }
        cp_commit();
    }

    const int T = nChunks * KW;
    for (int it = 0; it < T; ++it) {
        const int cc = it / KW;
        const int k  = it - cc * KW;
        const int stage = it & 1;

        cp_wait0();          // B(it) complete (own groups)
        __syncthreads();     // visibility; stage^1 and A buffer now free

        if (k == 0) {
            for (int g = tid; g < 2176; g += 128) {
                int plane = g >= 1088;
                int rem = plane ? g - 1088 : g;
                int r = rem >> 3;
                int c = rem & 7;
                int tok = i0 - 4 + r;
                uint32_t off = plane * 17408 + r * 128 + ((c ^ (r & 7)) << 4);
                if (tok >= 0 && tok < N_TOK) {
                    cp_async16(sA + off, (plane ? Al : Ah) +
                               (size_t)tok * cpad + cc * 64 + c * 8);
                } else {
                    *(uint4*)(smem + off) = make_uint4(0, 0, 0, 0);
                }
            }
            cp_commit();     // A group (older than B-next below)
        }
        if (it + 1 < T) {
            int ncc = (it + 1) / KW;
            int nk  = (it + 1) - ncc * KW;
#pragma unroll
            for (int j = 0; j < 16; ++j) {
                int g = tid + j * 128;
                int plane = g >> 10;
                int r = (g >> 3) & 127;
                int c = g & 7;
                const __nv_bfloat16* src =
                    (plane ? Wl : Wh) + ((size_t)(nk * DH + o0 + r)) * cpad +
                    ncc * 64 + c * 8;
                uint32_t dst = sB + (stage ^ 1) * 32768 + plane * 16384 +
                               r * 128 + ((c ^ (r & 7)) << 4);
                cp_async16(dst, src);
            }
            cp_commit();     // B(it+1) stays in flight during compute
        }
        if (k == 0) {
            cp_wait1();      // drain A (B(it+1) may remain pending)
            __syncthreads();
        }

        // tap mask predicates
        uint32_t z[4][2];
#pragma unroll
        for (int tm = 0; tm < 4; ++tm)
#pragma unroll
            for (int h = 0; h < 2; ++h) z[tm][h] = (mrow[tm][h] >> k) & 1u;

        // ---- compute: 4 k16-steps ----
#pragma unroll
        for (int ks = 0; ks < 4; ++ks) {
            uint32_t afr[2][4][4];   // [plane][tm][4]
#pragma unroll
            for (int p = 0; p < 2; ++p)
#pragma unroll
                for (int tm = 0; tm < 4; ++tm) {
                    int r = mw * 64 + tm * 16 + (lane & 15) + k;   // tap shift
                    int c = ks * 2 + (lane >> 4);
                    uint32_t addr = sA + p * 17408 + r * 128 + ((c ^ (r & 7)) << 4);
                    ldm4(afr[p][tm], addr);
                }
#pragma unroll
            for (int p = 0; p < 2; ++p)
#pragma unroll
                for (int tm = 0; tm < 4; ++tm) {
                    if (!z[tm][0]) { afr[p][tm][0] = 0u; afr[p][tm][2] = 0u; }
                    if (!z[tm][1]) { afr[p][tm][1] = 0u; afr[p][tm][3] = 0u; }
                }
            uint32_t bfr[2][4][4];   // [plane][nb(n16)][4]
#pragma unroll
            for (int p = 0; p < 2; ++p)
#pragma unroll
                for (int nb = 0; nb < 4; ++nb) {
                    int r = nw * 64 + nb * 16 + (((lane >> 4) & 1) << 3) + (lane & 7);
                    int c = ks * 2 + ((lane >> 3) & 1);
                    uint32_t addr = sB + stage * 32768 + p * 16384 +
                                    r * 128 + ((c ^ (r & 7)) << 4);
                    ldm4(bfr[p][nb], addr);
                }
            // product-outermost: same-acc MMAs spaced 32 apart
#pragma unroll
            for (int pr = 0; pr < 3; ++pr) {
                const int ap = (pr == 2) ? 1 : 0;
                const int bp = (pr == 1) ? 1 : 0;
#pragma unroll
                for (int tm = 0; tm < 4; ++tm)
#pragma unroll
                    for (int nb = 0; nb < 4; ++nb)
#pragma unroll
                        for (int hf = 0; hf < 2; ++hf)
                            mma16816(acc[tm][nb * 2 + hf], afr[ap][tm],
                                     bfr[bp][nb][hf * 2], bfr[bp][nb][hf * 2 + 1]);
            }
        }
    }

    // ---- epilogue: bias + ReLU + BN ----
#pragma unroll
    for (int tm = 0; tm < 4; ++tm) {
        int row = i0 + mw * 64 + tm * 16 + (lane >> 2);
#pragma unroll
        for (int n8 = 0; n8 < 8; ++n8) {
            int o = o0 + nw * 64 + n8 * 8 + (lane & 3) * 2;
            float s0 = gamma[o]     * rsqrtf(var[o]     + BN_EPS);
            float s1 = gamma[o + 1] * rsqrtf(var[o + 1] + BN_EPS);
            float h0 = beta[o]     - mean[o]     * s0;
            float h1 = beta[o + 1] - mean[o + 1] * s1;
            float bi0 = bias[o], bi1 = bias[o + 1];

            float v0 = fmaxf(acc[tm][n8][0] + bi0, 0.0f) * s0 + h0;
            float v1 = fmaxf(acc[tm][n8][1] + bi1, 0.0f) * s1 + h1;
            float v2 = fmaxf(acc[tm][n8][2] + bi0, 0.0f) * s0 + h0;
            float v3 = fmaxf(acc[tm][n8][3] + bi1, 0.0f) * s1 + h1;

            if (outFp32) {
                *(float2*)&outF[(size_t)row * DH + o]       = make_float2(v0, v1);
                *(float2*)&outF[(size_t)(row + 8) * DH + o] = make_float2(v2, v3);
            } else {
                __nv_bfloat16 a0 = __float2bfloat16(v0), a1 = __float2bfloat16(v1);
                __nv_bfloat16 a2 = __float2bfloat16(v2), a3 = __float2bfloat16(v3);
                __nv_bfloat16 l0 = __float2bfloat16(v0 - __bfloat162float(a0));
                __nv_bfloat16 l1 = __float2bfloat16(v1 - __bfloat162float(a1));
                __nv_bfloat16 l2 = __float2bfloat16(v2 - __bfloat162float(a2));
                __nv_bfloat16 l3 = __float2bfloat16(v3 - __bfloat162float(a3));
                unsigned hp0 = (unsigned)*(unsigned short*)&a0 |
                               ((unsigned)*(unsigned short*)&a1 << 16);
                unsigned lp0 = (unsigned)*(unsigned short*)&l0 |
                               ((unsigned)*(unsigned short*)&l1 << 16);
                unsigned hp1 = (unsigned)*(unsigned short*)&a2 |
                               ((unsigned)*(unsigned short*)&a3 << 16);
                unsigned lp1 = (unsigned)*(unsigned short*)&l2 |
                               ((unsigned)*(unsigned short*)&l3 << 16);
                *(unsigned*)&outH[(size_t)row * DH + o]       = hp0;
                *(unsigned*)&outL[(size_t)row * DH + o]       = lp0;
                *(unsigned*)&outH[(size_t)(row + 8) * DH + o] = hp1;
                *(unsigned*)&outL[(size_t)(row + 8) * DH + o] = lp1;
            }
        }
    }
}

// ---------------------------------------------------------------------------
__global__ void final_kernel(const float* __restrict__ h,
                             const float* __restrict__ wl,
                             const float* __restrict__ bl,
                             float* __restrict__ out)
{
    int gwarp = (blockIdx.x * blockDim.x + threadIdx.x) >> 5;
    int lane  = threadIdx.x & 31;
    if (gwarp >= N_TOK) return;

    const float4* hv = (const float4*)(h + (size_t)gwarp * DH);
    const float4* w0 = (const float4*)(wl);
    const float4* w1 = (const float4*)(wl + DH);

    float s0 = 0.0f, s1 = 0.0f;
    for (int j = lane; j < DH / 4; j += 32) {
        float4 a  = hv[j];
        float4 c0 = w0[j];
        float4 c1 = w1[j];
        s0 += a.x * c0.x + a.y * c0.y + a.z * c0.z + a.w * c0.w;
        s1 += a.x * c1.x + a.y * c1.y + a.z * c1.z + a.w * c1.w;
    }
#pragma unroll
    for (int off = 16; off > 0; off >>= 1) {
        s0 += __shfl_xor_sync(0xFFFFFFFFu, s0, off);
        s1 += __shfl_xor_sync(0xFFFFFFFFu, s1, off);
    }
    if (lane == 0) {
        float z0 = s0 + bl[0];
        float z1 = s1 + bl[1];
        float mx = fmaxf(z0, z1);
        float e0 = expf(z0 - mx);
        float e1 = expf(z1 - mx);
        float inv = 1.0f / (e0 + e1);
        out[(size_t)gwarp * 2 + 0] = z0;
        out[(size_t)gwarp * 2 + 1] = z1;
        out[(size_t)2 * N_TOK + (size_t)gwarp * 2 + 0] = e0 * inv;
        out[(size_t)2 * N_TOK + (size_t)gwarp * 2 + 1] = e1 * inv;
    }
}

// ---------------------------------------------------------------------------
extern "C" void kernel_launch(void* const* d_in, const int* in_sizes, int n_in,
                              void* d_out, int out_size) {
    const float* x   = (const float*)d_in[0];
    const int*   seg = (const int*)d_in[1];      // int32 (JAX x64 disabled)
    const float* w1  = (const float*)d_in[2];
    const float* b1  = (const float*)d_in[3];
    const float* g1  = (const float*)d_in[4];
    const float* be1 = (const float*)d_in[5];
    const float* m1  = (const float*)d_in[6];
    const float* v1  = (const float*)d_in[7];
    const float* w2  = (const float*)d_in[8];
    const float* b2  = (const float*)d_in[9];
    const float* g2  = (const float*)d_in[10];
    const float* be2 = (const float*)d_in[11];
    const float* m2  = (const float*)d_in[12];
    const float* v2  = (const float*)d_in[13];
    const float* wl  = (const float*)d_in[14];
    const float* bl  = (const float*)d_in[15];
    float* out = (float*)d_out;

    __nv_bfloat16 *xh, *xl, *w1h, *w1l, *w2h, *w2l, *h1h, *h1l;
    float* h2;
    unsigned* mask;
    cudaGetSymbolAddress((void**)&xh,  g_xh);
    cudaGetSymbolAddress((void**)&xl,  g_xl);
    cudaGetSymbolAddress((void**)&w1h, g_w1h);
    cudaGetSymbolAddress((void**)&w1l, g_w1l);
    cudaGetSymbolAddress((void**)&w2h, g_w2h);
    cudaGetSymbolAddress((void**)&w2l, g_w2l);
    cudaGetSymbolAddress((void**)&h1h, g_h1h);
    cudaGetSymbolAddress((void**)&h1l, g_h1l);
    cudaGetSymbolAddress((void**)&h2,  g_h2);
    cudaGetSymbolAddress((void**)&mask, g_mask);

    cudaFuncSetAttribute(conv_mma_kernel,
                         cudaFuncAttributeMaxDynamicSharedMemorySize, SMEM_TOTAL);
    cudaFuncSetAttribute(wsplit_kernel,
                         cudaFuncAttributeMaxDynamicSharedMemorySize,
                         DH * KW * (int)sizeof(float));

    mask_kernel<<<(N_TOK + 255) / 256, 256>>>(seg, mask);

    {
        size_t tx = (size_t)N_TOK * CP1;
        split_x_kernel<<<(unsigned)((tx + 255) / 256), 256>>>(x, xh, xl);
        wsplit_kernel<<<DH, 512, DIN * KW * sizeof(float)>>>(w1, w1h, w1l, DIN, CP1);
        wsplit_kernel<<<DH, 512, DH * KW * sizeof(float)>>>(w2, w2h, w2l, DH, DH);
    }

    dim3 grid(N_TOK / 128, DH / 128);   // m fastest -> B panel hot in L2
    conv_mma_kernel<<<grid, 128, SMEM_TOTAL>>>(
        xh, xl, CP1, CP1 / 64, w1h, w1l, mask,
        b1, g1, be1, m1, v1, 0, nullptr, h1h, h1l);
    conv_mma_kernel<<<grid, 128, SMEM_TOTAL>>>(
        h1h, h1l, DH, DH / 64, w2h, w2l, mask,
        b2, g2, be2, m2, v2, 1, h2, nullptr, nullptr);

    final_kernel<<<(N_TOK * 32 + 127) / 128, 128>>>(h2, wl, bl, out);
}

// round 15
// speedup vs baseline: 5.6537x; 1.4363x over previous
#include <cuda_runtime.h>
#include <cuda_fp16.h>
#include <cstdint>
#include <math.h>

// ---------------------------------------------------------------------------
// PainHead via warp-level fp16 mma.sync (m16n8k16) 2-product split-GEMM.
// R13 insight: we were AT the legacy-HMMA roofline with bf16x3 (3 MMAs per
// logical FLOP). fp16's 11-bit mantissa lets us quantize A once (err ~2^-12)
// and split only W into fp16 hi/lo: D = A*Wh + A*Wl  => 2 MMAs, floor 2.97ms.
// out[i,o] = BN(ReLU(b[o] + sum_{k,c} mask(i,k) * A[i+k-4,c] * W[o,c,k]))
// CTA tile: 128 tokens x 128 outputs; K-loop: 64-ch chunks x 9 taps.
// ---------------------------------------------------------------------------

#define N_TOK 8192
#define DIN   600
#define CP1   640
#define DH    2048
#define KW    9
#define BN_EPS 1e-5f

// ---------------- device scratch ----------------
__device__ __half g_xe [(size_t)N_TOK * CP1];
__device__ __half g_w1h[(size_t)KW * DH * CP1];
__device__ __half g_w1l[(size_t)KW * DH * CP1];
__device__ __half g_w2h[(size_t)KW * DH * DH];
__device__ __half g_w2l[(size_t)KW * DH * DH];
__device__ __half g_h1 [(size_t)N_TOK * DH];
__device__ float  g_h2 [(size_t)N_TOK * DH];
__device__ unsigned g_mask[N_TOK];

// ---------------- helpers ----------------
__device__ __forceinline__ uint32_t smem_u32(const void* p) {
    uint32_t a;
    asm("{ .reg .u64 t; cvta.to.shared.u64 t, %1; cvt.u32.u64 %0, t; }"
        : "=r"(a) : "l"(p));
    return a;
}
__device__ __forceinline__ void ldm4(uint32_t* r, uint32_t addr) {
    asm volatile("ldmatrix.sync.aligned.m8n8.x4.shared.b16 {%0,%1,%2,%3}, [%4];"
                 : "=r"(r[0]), "=r"(r[1]), "=r"(r[2]), "=r"(r[3]) : "r"(addr));
}
__device__ __forceinline__ void mma16816(float* d, const uint32_t* a,
                                         uint32_t b0, uint32_t b1) {
    asm volatile(
        "mma.sync.aligned.m16n8k16.row.col.f32.f16.f16.f32 "
        "{%0,%1,%2,%3}, {%4,%5,%6,%7}, {%8,%9}, {%0,%1,%2,%3};"
        : "+f"(d[0]), "+f"(d[1]), "+f"(d[2]), "+f"(d[3])
        : "r"(a[0]), "r"(a[1]), "r"(a[2]), "r"(a[3]), "r"(b0), "r"(b1));
}
__device__ __forceinline__ void cp_async16(uint32_t smem_addr, const void* gptr) {
    asm volatile("cp.async.cg.shared.global [%0], [%1], 16;"
                 :: "r"(smem_addr), "l"(gptr));
}
__device__ __forceinline__ void cp_commit() {
    asm volatile("cp.async.commit_group;");
}
__device__ __forceinline__ void cp_wait0() {
    asm volatile("cp.async.wait_group 0;");
}
__device__ __forceinline__ void cp_wait1() {
    asm volatile("cp.async.wait_group 1;");
}

// ---------------- smem layout ----------------
// A ext: 1 plane x 136 rows x 128B = 17408
// B:     2 stages x 2 planes (Wh/Wl) x 128 rows x 128B = 65536
#define SM_B       17408
#define SMEM_TOTAL 82944

// ---------------------------------------------------------------------------
__global__ void mask_kernel(const int* __restrict__ seg, unsigned* __restrict__ bits) {
    int i = blockIdx.x * blockDim.x + threadIdx.x;
    if (i >= N_TOK) return;
    int s = seg[i];
    unsigned b = 0;
#pragma unroll
    for (int k = 0; k < KW; ++k) {
        int j = i + k - KW / 2;
        if (j >= 0 && j < N_TOK && seg[j] == s) b |= (1u << k);
    }
    bits[i] = b;
}

__global__ void split_x_kernel(const float* __restrict__ x,
                               __half* __restrict__ xe) {
    size_t idx = (size_t)blockIdx.x * blockDim.x + threadIdx.x;
    if (idx >= (size_t)N_TOK * CP1) return;
    int c = (int)(idx % CP1);
    int r = (int)(idx / CP1);
    float v = (c < DIN) ? x[(size_t)r * DIN + c] : 0.0f;
    xe[idx] = __float2half(v);
}

// Coalesced weight split: one block (512 thr) per output row o.
// float4 loads into smem; packed 2xfp16 32-bit stores (hi and residual-lo).
__global__ void wsplit_kernel(const float* __restrict__ w,
                              __half* __restrict__ wh,
                              __half* __restrict__ wl,
                              int C, int cpad) {
    extern __shared__ float sw[];
    const int o   = blockIdx.x;
    const int tid = threadIdx.x;
    const int nt  = blockDim.x;
    const float4* src4 = (const float4*)(w + (size_t)o * C * KW);
    const int total4 = (C * KW) / 4;          // 5400/4, 18432/4 both exact
    for (int i = tid; i < total4; i += nt) ((float4*)sw)[i] = src4[i];
    __syncthreads();
#pragma unroll
    for (int k = 0; k < KW; ++k) {
        size_t base = ((size_t)k * DH + o) * cpad;
        for (int c2 = tid; c2 < cpad / 2; c2 += nt) {
            int c = c2 * 2;
            float v0 = (c     < C) ? sw[c * KW + k]       : 0.0f;
            float v1 = (c + 1 < C) ? sw[(c + 1) * KW + k] : 0.0f;
            __half h0 = __float2half(v0);
            __half h1 = __float2half(v1);
            __half l0 = __float2half(v0 - __half2float(h0));
            __half l1 = __float2half(v1 - __half2float(h1));
            unsigned hp = (unsigned)*(unsigned short*)&h0 |
                          ((unsigned)*(unsigned short*)&h1 << 16);
            unsigned lp = (unsigned)*(unsigned short*)&l0 |
                          ((unsigned)*(unsigned short*)&l1 << 16);
            *(unsigned*)&wh[base + c] = hp;
            *(unsigned*)&wl[base + c] = lp;
        }
    }
}

// ---------------------------------------------------------------------------
// Conv-GEMM via fp16 mma.sync. 128 threads = 4 warps: warp grid 2(m64) x 2(n64).
// cp.async 2-stage B pipeline; single-plane A-ext filled per 64-ch chunk.
// ---------------------------------------------------------------------------
__global__ __launch_bounds__(128)
void conv_mma_kernel(
    const __half* __restrict__ A,
    int cpad, int nChunks,
    const __half* __restrict__ Wh, const __half* __restrict__ Wl,
    const unsigned* __restrict__ maskbits,
    const float* __restrict__ bias, const float* __restrict__ gamma,
    const float* __restrict__ beta, const float* __restrict__ mean,
    const float* __restrict__ var,
    int outFp32, float* __restrict__ outF, __half* __restrict__ outH)
{
    extern __shared__ __align__(128) char smem[];
    const uint32_t sA = smem_u32(smem);
    const uint32_t sB = sA + SM_B;

    const int tid  = threadIdx.x;
    const int wid  = tid >> 5;
    const int lane = tid & 31;
    const int mw   = wid & 1;     // m warp: 64 rows each
    const int nw   = wid >> 1;    // n warp: 64 cols each
    const int i0   = blockIdx.x * 128;
    const int o0   = blockIdx.y * 128;

    float acc[4][8][4];
#pragma unroll
    for (int tm = 0; tm < 4; ++tm)
#pragma unroll
        for (int n8 = 0; n8 < 8; ++n8)
#pragma unroll
            for (int q = 0; q < 4; ++q) acc[tm][n8][q] = 0.0f;

    unsigned mrow[4][2];
#pragma unroll
    for (int tm = 0; tm < 4; ++tm)
#pragma unroll
        for (int h = 0; h < 2; ++h)
            mrow[tm][h] = maskbits[i0 + mw * 64 + tm * 16 + h * 8 + (lane >> 2)];

    // prologue: issue B(0) into stage 0 (2 planes x 128 rows x 8 chunks)
    {
#pragma unroll
        for (int j = 0; j < 16; ++j) {
            int g = tid + j * 128;
            int plane = g >> 10;
            int r = (g >> 3) & 127;
            int c = g & 7;
            const __half* src =
                (plane ? Wl : Wh) + ((size_t)(o0 + r)) * cpad + c * 8;
            uint32_t dst = sB + plane * 16384 + r * 128 + ((c ^ (r & 7)) << 4);
            cp_async16(dst, src);
        }
        cp_commit();
    }

    const int T = nChunks * KW;
    for (int it = 0; it < T; ++it) {
        const int cc = it / KW;
        const int k  = it - cc * KW;
        const int stage = it & 1;

        cp_wait0();          // B(it) complete
        __syncthreads();     // visibility; stage^1 and A buffer now free

        if (k == 0) {
            // fill single-plane A-ext for chunk cc
            for (int g = tid; g < 1088; g += 128) {
                int r = g >> 3;
                int c = g & 7;
                int tok = i0 - 4 + r;
                uint32_t off = r * 128 + ((c ^ (r & 7)) << 4);
                if (tok >= 0 && tok < N_TOK) {
                    cp_async16(sA + off, A + (size_t)tok * cpad + cc * 64 + c * 8);
                } else {
                    *(uint4*)(smem + off) = make_uint4(0, 0, 0, 0);
                }
            }
            cp_commit();     // A group (older than B-next below)
        }
        if (it + 1 < T) {
            int ncc = (it + 1) / KW;
            int nk  = (it + 1) - ncc * KW;
#pragma unroll
            for (int j = 0; j < 16; ++j) {
                int g = tid + j * 128;
                int plane = g >> 10;
                int r = (g >> 3) & 127;
                int c = g & 7;
                const __half* src =
                    (plane ? Wl : Wh) + ((size_t)(nk * DH + o0 + r)) * cpad +
                    ncc * 64 + c * 8;
                uint32_t dst = sB + (stage ^ 1) * 32768 + plane * 16384 +
                               r * 128 + ((c ^ (r & 7)) << 4);
                cp_async16(dst, src);
            }
            cp_commit();     // B(it+1) stays in flight during compute
        }
        if (k == 0) {
            cp_wait1();      // drain A (B(it+1) may remain pending)
            __syncthreads();
        }

        // tap mask predicates
        uint32_t z[4][2];
#pragma unroll
        for (int tm = 0; tm < 4; ++tm)
#pragma unroll
            for (int h = 0; h < 2; ++h) z[tm][h] = (mrow[tm][h] >> k) & 1u;

        // ---- compute: 4 k16-steps ----
#pragma unroll
        for (int ks = 0; ks < 4; ++ks) {
            uint32_t afr[4][4];   // [tm][4]
#pragma unroll
            for (int tm = 0; tm < 4; ++tm) {
                int r = mw * 64 + tm * 16 + (lane & 15) + k;   // tap shift
                int c = ks * 2 + (lane >> 4);
                uint32_t addr = sA + r * 128 + ((c ^ (r & 7)) << 4);
                ldm4(afr[tm], addr);
            }
#pragma unroll
            for (int tm = 0; tm < 4; ++tm) {
                if (!z[tm][0]) { afr[tm][0] = 0u; afr[tm][2] = 0u; }
                if (!z[tm][1]) { afr[tm][1] = 0u; afr[tm][3] = 0u; }
            }
            uint32_t bfr[2][4][4];   // [plane][nb(n16)][4]
#pragma unroll
            for (int p = 0; p < 2; ++p)
#pragma unroll
                for (int nb = 0; nb < 4; ++nb) {
                    int r = nw * 64 + nb * 16 + (((lane >> 4) & 1) << 3) + (lane & 7);
                    int c = ks * 2 + ((lane >> 3) & 1);
                    uint32_t addr = sB + stage * 32768 + p * 16384 +
                                    r * 128 + ((c ^ (r & 7)) << 4);
                    ldm4(bfr[p][nb], addr);
                }
            // 2 products: A*Wh + A*Wl; same-acc MMAs spaced 32 apart
#pragma unroll
            for (int bp = 0; bp < 2; ++bp)
#pragma unroll
                for (int tm = 0; tm < 4; ++tm)
#pragma unroll
                    for (int nb = 0; nb < 4; ++nb)
#pragma unroll
                        for (int hf = 0; hf < 2; ++hf)
                            mma16816(acc[tm][nb * 2 + hf], afr[tm],
                                     bfr[bp][nb][hf * 2], bfr[bp][nb][hf * 2 + 1]);
        }
    }

    // ---- epilogue: bias + ReLU + BN ----
#pragma unroll
    for (int tm = 0; tm < 4; ++tm) {
        int row = i0 + mw * 64 + tm * 16 + (lane >> 2);
#pragma unroll
        for (int n8 = 0; n8 < 8; ++n8) {
            int o = o0 + nw * 64 + n8 * 8 + (lane & 3) * 2;
            float s0 = gamma[o]     * rsqrtf(var[o]     + BN_EPS);
            float s1 = gamma[o + 1] * rsqrtf(var[o + 1] + BN_EPS);
            float h0 = beta[o]     - mean[o]     * s0;
            float h1 = beta[o + 1] - mean[o + 1] * s1;
            float bi0 = bias[o], bi1 = bias[o + 1];

            float v0 = fmaxf(acc[tm][n8][0] + bi0, 0.0f) * s0 + h0;
            float v1 = fmaxf(acc[tm][n8][1] + bi1, 0.0f) * s1 + h1;
            float v2 = fmaxf(acc[tm][n8][2] + bi0, 0.0f) * s0 + h0;
            float v3 = fmaxf(acc[tm][n8][3] + bi1, 0.0f) * s1 + h1;

            if (outFp32) {
                *(float2*)&outF[(size_t)row * DH + o]       = make_float2(v0, v1);
                *(float2*)&outF[(size_t)(row + 8) * DH + o] = make_float2(v2, v3);
            } else {
                __half a0 = __float2half(v0), a1 = __float2half(v1);
                __half a2 = __float2half(v2), a3 = __float2half(v3);
                unsigned p0 = (unsigned)*(unsigned short*)&a0 |
                              ((unsigned)*(unsigned short*)&a1 << 16);
                unsigned p1 = (unsigned)*(unsigned short*)&a2 |
                              ((unsigned)*(unsigned short*)&a3 << 16);
                *(unsigned*)&outH[(size_t)row * DH + o]       = p0;
                *(unsigned*)&outH[(size_t)(row + 8) * DH + o] = p1;
            }
        }
    }
}

// ---------------------------------------------------------------------------
__global__ void final_kernel(const float* __restrict__ h,
                             const float* __restrict__ wl,
                             const float* __restrict__ bl,
                             float* __restrict__ out)
{
    int gwarp = (blockIdx.x * blockDim.x + threadIdx.x) >> 5;
    int lane  = threadIdx.x & 31;
    if (gwarp >= N_TOK) return;

    const float4* hv = (const float4*)(h + (size_t)gwarp * DH);
    const float4* w0 = (const float4*)(wl);
    const float4* w1 = (const float4*)(wl + DH);

    float s0 = 0.0f, s1 = 0.0f;
    for (int j = lane; j < DH / 4; j += 32) {
        float4 a  = hv[j];
        float4 c0 = w0[j];
        float4 c1 = w1[j];
        s0 += a.x * c0.x + a.y * c0.y + a.z * c0.z + a.w * c0.w;
        s1 += a.x * c1.x + a.y * c1.y + a.z * c1.z + a.w * c1.w;
    }
#pragma unroll
    for (int off = 16; off > 0; off >>= 1) {
        s0 += __shfl_xor_sync(0xFFFFFFFFu, s0, off);
        s1 += __shfl_xor_sync(0xFFFFFFFFu, s1, off);
    }
    if (lane == 0) {
        float z0 = s0 + bl[0];
        float z1 = s1 + bl[1];
        float mx = fmaxf(z0, z1);
        float e0 = expf(z0 - mx);
        float e1 = expf(z1 - mx);
        float inv = 1.0f / (e0 + e1);
        out[(size_t)gwarp * 2 + 0] = z0;
        out[(size_t)gwarp * 2 + 1] = z1;
        out[(size_t)2 * N_TOK + (size_t)gwarp * 2 + 0] = e0 * inv;
        out[(size_t)2 * N_TOK + (size_t)gwarp * 2 + 1] = e1 * inv;
    }
}

// ---------------------------------------------------------------------------
extern "C" void kernel_launch(void* const* d_in, const int* in_sizes, int n_in,
                              void* d_out, int out_size) {
    const float* x   = (const float*)d_in[0];
    const int*   seg = (const int*)d_in[1];      // int32 (JAX x64 disabled)
    const float* w1  = (const float*)d_in[2];
    const float* b1  = (const float*)d_in[3];
    const float* g1  = (const float*)d_in[4];
    const float* be1 = (const float*)d_in[5];
    const float* m1  = (const float*)d_in[6];
    const float* v1  = (const float*)d_in[7];
    const float* w2  = (const float*)d_in[8];
    const float* b2  = (const float*)d_in[9];
    const float* g2  = (const float*)d_in[10];
    const float* be2 = (const float*)d_in[11];
    const float* m2  = (const float*)d_in[12];
    const float* v2  = (const float*)d_in[13];
    const float* wl  = (const float*)d_in[14];
    const float* bl  = (const float*)d_in[15];
    float* out = (float*)d_out;

    __half *xe, *w1h, *w1l, *w2h, *w2l, *h1;
    float* h2;
    unsigned* mask;
    cudaGetSymbolAddress((void**)&xe,  g_xe);
    cudaGetSymbolAddress((void**)&w1h, g_w1h);
    cudaGetSymbolAddress((void**)&w1l, g_w1l);
    cudaGetSymbolAddress((void**)&w2h, g_w2h);
    cudaGetSymbolAddress((void**)&w2l, g_w2l);
    cudaGetSymbolAddress((void**)&h1,  g_h1);
    cudaGetSymbolAddress((void**)&h2,  g_h2);
    cudaGetSymbolAddress((void**)&mask, g_mask);

    cudaFuncSetAttribute(conv_mma_kernel,
                         cudaFuncAttributeMaxDynamicSharedMemorySize, SMEM_TOTAL);
    cudaFuncSetAttribute(wsplit_kernel,
                         cudaFuncAttributeMaxDynamicSharedMemorySize,
                         DH * KW * (int)sizeof(float));

    mask_kernel<<<(N_TOK + 255) / 256, 256>>>(seg, mask);

    {
        size_t tx = (size_t)N_TOK * CP1;
        split_x_kernel<<<(unsigned)((tx + 255) / 256), 256>>>(x, xe);
        wsplit_kernel<<<DH, 512, DIN * KW * sizeof(float)>>>(w1, w1h, w1l, DIN, CP1);
        wsplit_kernel<<<DH, 512, DH * KW * sizeof(float)>>>(w2, w2h, w2l, DH, DH);
    }

    dim3 grid(N_TOK / 128, DH / 128);   // m fastest -> B panel hot in L2
    conv_mma_kernel<<<grid, 128, SMEM_TOTAL>>>(
        xe, CP1, CP1 / 64, w1h, w1l, mask,
        b1, g1, be1, m1, v1, 0, nullptr, h1);
    conv_mma_kernel<<<grid, 128, SMEM_TOTAL>>>(
        h1, DH, DH / 64, w2h, w2l, mask,
        b2, g2, be2, m2, v2, 1, h2, nullptr);

    final_kernel<<<(N_TOK * 32 + 127) / 128, 128>>>(h2, wl, bl, out);
}

// round 16
// speedup vs baseline: 5.8071x; 1.0271x over previous
#include <cuda_runtime.h>
#include <cuda_fp16.h>
#include <cstdint>
#include <math.h>

// ---------------------------------------------------------------------------
// PainHead via warp-level fp16 mma.sync (m16n8k16), SINGLE product.
// R15 insight: A-quantization error (measured 2.88e-4) and W-quantization
// error are the same magnitude; adding W-quant costs only sqrt(2)x error
// (~4-5e-4 < 1e-3) and halves the MMA count -> tensor floor 1.49 ms.
// out[i,o] = BN(ReLU(b[o] + sum_{k,c} mask(i,k) * A[i+k-4,c] * W[o,c,k]))
// CTA tile: 128 tokens x 128 outputs; K-loop: 64-ch chunks x 9 taps.
// Fully async pipeline: B double-staged per tap, A-ext double-buffered per
// chunk (issued at tap k=8 of the previous chunk) -> one wait_group 0 per
// iteration, always overlapped by compute.
// ---------------------------------------------------------------------------

#define N_TOK 8192
#define DIN   600
#define CP1   640
#define DH    2048
#define KW    9
#define BN_EPS 1e-5f

// ---------------- device scratch ----------------
__device__ __half g_xe [(size_t)N_TOK * CP1];
__device__ __half g_w1 [(size_t)KW * DH * CP1];
__device__ __half g_w2 [(size_t)KW * DH * DH];
__device__ __half g_h1 [(size_t)N_TOK * DH];
__device__ float  g_h2 [(size_t)N_TOK * DH];
__device__ unsigned g_mask[N_TOK];

// ---------------- helpers ----------------
__device__ __forceinline__ uint32_t smem_u32(const void* p) {
    uint32_t a;
    asm("{ .reg .u64 t; cvta.to.shared.u64 t, %1; cvt.u32.u64 %0, t; }"
        : "=r"(a) : "l"(p));
    return a;
}
__device__ __forceinline__ void ldm4(uint32_t* r, uint32_t addr) {
    asm volatile("ldmatrix.sync.aligned.m8n8.x4.shared.b16 {%0,%1,%2,%3}, [%4];"
                 : "=r"(r[0]), "=r"(r[1]), "=r"(r[2]), "=r"(r[3]) : "r"(addr));
}
__device__ __forceinline__ void mma16816(float* d, const uint32_t* a,
                                         uint32_t b0, uint32_t b1) {
    asm volatile(
        "mma.sync.aligned.m16n8k16.row.col.f32.f16.f16.f32 "
        "{%0,%1,%2,%3}, {%4,%5,%6,%7}, {%8,%9}, {%0,%1,%2,%3};"
        : "+f"(d[0]), "+f"(d[1]), "+f"(d[2]), "+f"(d[3])
        : "r"(a[0]), "r"(a[1]), "r"(a[2]), "r"(a[3]), "r"(b0), "r"(b1));
}
__device__ __forceinline__ void cp_async16(uint32_t smem_addr, const void* gptr) {
    asm volatile("cp.async.cg.shared.global [%0], [%1], 16;"
                 :: "r"(smem_addr), "l"(gptr));
}
__device__ __forceinline__ void cp_commit() {
    asm volatile("cp.async.commit_group;");
}
__device__ __forceinline__ void cp_wait0() {
    asm volatile("cp.async.wait_group 0;");
}

// ---------------- smem layout ----------------
// A ext: 2 bufs x 136 rows x 128B = 34816
// B:     2 stages x 128 rows x 128B = 32768
#define SM_B       34816
#define SMEM_TOTAL 67584

// ---------------------------------------------------------------------------
__global__ void mask_kernel(const int* __restrict__ seg, unsigned* __restrict__ bits) {
    int i = blockIdx.x * blockDim.x + threadIdx.x;
    if (i >= N_TOK) return;
    int s = seg[i];
    unsigned b = 0;
#pragma unroll
    for (int k = 0; k < KW; ++k) {
        int j = i + k - KW / 2;
        if (j >= 0 && j < N_TOK && seg[j] == s) b |= (1u << k);
    }
    bits[i] = b;
}

__global__ void split_x_kernel(const float* __restrict__ x,
                               __half* __restrict__ xe) {
    size_t idx = (size_t)blockIdx.x * blockDim.x + threadIdx.x;
    if (idx >= (size_t)N_TOK * CP1) return;
    int c = (int)(idx % CP1);
    int r = (int)(idx / CP1);
    float v = (c < DIN) ? x[(size_t)r * DIN + c] : 0.0f;
    xe[idx] = __float2half(v);
}

// Coalesced weight convert: one block (512 thr) per output row o.
// w[o][c][k] f32 -> wt[k][o][cpad] fp16 (single plane).
__global__ void wcvt_kernel(const float* __restrict__ w,
                            __half* __restrict__ wh,
                            int C, int cpad) {
    extern __shared__ float sw[];
    const int o   = blockIdx.x;
    const int tid = threadIdx.x;
    const int nt  = blockDim.x;
    const float4* src4 = (const float4*)(w + (size_t)o * C * KW);
    const int total4 = (C * KW) / 4;          // 5400/4, 18432/4 both exact
    for (int i = tid; i < total4; i += nt) ((float4*)sw)[i] = src4[i];
    __syncthreads();
#pragma unroll
    for (int k = 0; k < KW; ++k) {
        size_t base = ((size_t)k * DH + o) * cpad;
        for (int c2 = tid; c2 < cpad / 2; c2 += nt) {
            int c = c2 * 2;
            float v0 = (c     < C) ? sw[c * KW + k]       : 0.0f;
            float v1 = (c + 1 < C) ? sw[(c + 1) * KW + k] : 0.0f;
            __half h0 = __float2half(v0);
            __half h1 = __float2half(v1);
            unsigned hp = (unsigned)*(unsigned short*)&h0 |
                          ((unsigned)*(unsigned short*)&h1 << 16);
            *(unsigned*)&wh[base + c] = hp;
        }
    }
}

// ---------------------------------------------------------------------------
// Conv-GEMM via fp16 mma.sync, single product. 128 threads = 4 warps:
// warp grid 2(m64) x 2(n64). Fully async A/B staging.
// ---------------------------------------------------------------------------
__global__ __launch_bounds__(128)
void conv_mma_kernel(
    const __half* __restrict__ A,
    int cpad, int nChunks,
    const __half* __restrict__ W,
    const unsigned* __restrict__ maskbits,
    const float* __restrict__ bias, const float* __restrict__ gamma,
    const float* __restrict__ beta, const float* __restrict__ mean,
    const float* __restrict__ var,
    int outFp32, float* __restrict__ outF, __half* __restrict__ outH)
{
    extern __shared__ __align__(128) char smem[];
    const uint32_t sA = smem_u32(smem);
    const uint32_t sB = sA + SM_B;

    const int tid  = threadIdx.x;
    const int wid  = tid >> 5;
    const int lane = tid & 31;
    const int mw   = wid & 1;     // m warp: 64 rows each
    const int nw   = wid >> 1;    // n warp: 64 cols each
    const int i0   = blockIdx.x * 128;
    const int o0   = blockIdx.y * 128;

    float acc[4][8][4];
#pragma unroll
    for (int tm = 0; tm < 4; ++tm)
#pragma unroll
        for (int n8 = 0; n8 < 8; ++n8)
#pragma unroll
            for (int q = 0; q < 4; ++q) acc[tm][n8][q] = 0.0f;

    unsigned mrow[4][2];
#pragma unroll
    for (int tm = 0; tm < 4; ++tm)
#pragma unroll
        for (int h = 0; h < 2; ++h)
            mrow[tm][h] = maskbits[i0 + mw * 64 + tm * 16 + h * 8 + (lane >> 2)];

    // ---- prologue: B(0) into stage 0, A(chunk 0) into buf 0, one group ----
    {
#pragma unroll
        for (int j = 0; j < 8; ++j) {
            int g = tid + j * 128;            // 0..1023 = 128 rows x 8 chunks
            int r = g >> 3;
            int c = g & 7;
            const __half* src = W + ((size_t)(o0 + r)) * cpad + c * 8;
            uint32_t dst = sB + r * 128 + ((c ^ (r & 7)) << 4);
            cp_async16(dst, src);
        }
        for (int g = tid; g < 1088; g += 128) {   // 136 rows x 8 chunks
            int r = g >> 3;
            int c = g & 7;
            int tok = i0 - 4 + r;
            uint32_t off = r * 128 + ((c ^ (r & 7)) << 4);
            if (tok >= 0 && tok < N_TOK) {
                cp_async16(sA + off, A + (size_t)tok * cpad + c * 8);
            } else {
                *(uint4*)(smem + off) = make_uint4(0, 0, 0, 0);
            }
        }
        cp_commit();
    }

    const int T = nChunks * KW;
    for (int it = 0; it < T; ++it) {
        const int cc = it / KW;
        const int k  = it - cc * KW;
        const int stage = it & 1;
        const int abuf  = cc & 1;

        cp_wait0();          // previous iteration's group (B(it) [+A(cc)])
        __syncthreads();     // visibility; write targets now free

        if (it + 1 < T) {
            int ncc = (it + 1) / KW;
            int nk  = (it + 1) - ncc * KW;
            // B(it+1) into the other stage
#pragma unroll
            for (int j = 0; j < 8; ++j) {
                int g = tid + j * 128;
                int r = g >> 3;
                int c = g & 7;
                const __half* src =
                    W + ((size_t)(nk * DH + o0 + r)) * cpad + ncc * 64 + c * 8;
                uint32_t dst = sB + (stage ^ 1) * 16384 +
                               r * 128 + ((c ^ (r & 7)) << 4);
                cp_async16(dst, src);
            }
            // at the last tap of chunk cc, also stage A(cc+1) into buf^1
            if (k == KW - 1) {
                for (int g = tid; g < 1088; g += 128) {
                    int r = g >> 3;
                    int c = g & 7;
                    int tok = i0 - 4 + r;
                    uint32_t off = (abuf ^ 1) * 17408 +
                                   r * 128 + ((c ^ (r & 7)) << 4);
                    if (tok >= 0 && tok < N_TOK) {
                        cp_async16(sA + off,
                                   A + (size_t)tok * cpad + (cc + 1) * 64 + c * 8);
                    } else {
                        *(uint4*)(smem + off) = make_uint4(0, 0, 0, 0);
                    }
                }
            }
            cp_commit();     // one group per iteration
        }

        // tap mask predicates
        uint32_t z[4][2];
#pragma unroll
        for (int tm = 0; tm < 4; ++tm)
#pragma unroll
            for (int h = 0; h < 2; ++h) z[tm][h] = (mrow[tm][h] >> k) & 1u;

        // ---- compute: 4 k16-steps ----
#pragma unroll
        for (int ks = 0; ks < 4; ++ks) {
            uint32_t afr[4][4];   // [tm][4]
#pragma unroll
            for (int tm = 0; tm < 4; ++tm) {
                int r = mw * 64 + tm * 16 + (lane & 15) + k;   // tap shift
                int c = ks * 2 + (lane >> 4);
                uint32_t addr = sA + abuf * 17408 +
                                r * 128 + ((c ^ (r & 7)) << 4);
                ldm4(afr[tm], addr);
            }
#pragma unroll
            for (int tm = 0; tm < 4; ++tm) {
                if (!z[tm][0]) { afr[tm][0] = 0u; afr[tm][2] = 0u; }
                if (!z[tm][1]) { afr[tm][1] = 0u; afr[tm][3] = 0u; }
            }
            uint32_t bfr[4][4];   // [nb(n16)][4]
#pragma unroll
            for (int nb = 0; nb < 4; ++nb) {
                int r = nw * 64 + nb * 16 + (((lane >> 4) & 1) << 3) + (lane & 7);
                int c = ks * 2 + ((lane >> 3) & 1);
                uint32_t addr = sB + stage * 16384 +
                                r * 128 + ((c ^ (r & 7)) << 4);
                ldm4(bfr[nb], addr);
            }
#pragma unroll
            for (int tm = 0; tm < 4; ++tm)
#pragma unroll
                for (int nb = 0; nb < 4; ++nb)
#pragma unroll
                    for (int hf = 0; hf < 2; ++hf)
                        mma16816(acc[tm][nb * 2 + hf], afr[tm],
                                 bfr[nb][hf * 2], bfr[nb][hf * 2 + 1]);
        }
    }

    // ---- epilogue: bias + ReLU + BN ----
#pragma unroll
    for (int tm = 0; tm < 4; ++tm) {
        int row = i0 + mw * 64 + tm * 16 + (lane >> 2);
#pragma unroll
        for (int n8 = 0; n8 < 8; ++n8) {
            int o = o0 + nw * 64 + n8 * 8 + (lane & 3) * 2;
            float s0 = gamma[o]     * rsqrtf(var[o]     + BN_EPS);
            float s1 = gamma[o + 1] * rsqrtf(var[o + 1] + BN_EPS);
            float h0 = beta[o]     - mean[o]     * s0;
            float h1 = beta[o + 1] - mean[o + 1] * s1;
            float bi0 = bias[o], bi1 = bias[o + 1];

            float v0 = fmaxf(acc[tm][n8][0] + bi0, 0.0f) * s0 + h0;
            float v1 = fmaxf(acc[tm][n8][1] + bi1, 0.0f) * s1 + h1;
            float v2 = fmaxf(acc[tm][n8][2] + bi0, 0.0f) * s0 + h0;
            float v3 = fmaxf(acc[tm][n8][3] + bi1, 0.0f) * s1 + h1;

            if (outFp32) {
                *(float2*)&outF[(size_t)row * DH + o]       = make_float2(v0, v1);
                *(float2*)&outF[(size_t)(row + 8) * DH + o] = make_float2(v2, v3);
            } else {
                __half a0 = __float2half(v0), a1 = __float2half(v1);
                __half a2 = __float2half(v2), a3 = __float2half(v3);
                unsigned p0 = (unsigned)*(unsigned short*)&a0 |
                              ((unsigned)*(unsigned short*)&a1 << 16);
                unsigned p1 = (unsigned)*(unsigned short*)&a2 |
                              ((unsigned)*(unsigned short*)&a3 << 16);
                *(unsigned*)&outH[(size_t)row * DH + o]       = p0;
                *(unsigned*)&outH[(size_t)(row + 8) * DH + o] = p1;
            }
        }
    }
}

// ---------------------------------------------------------------------------
__global__ void final_kernel(const float* __restrict__ h,
                             const float* __restrict__ wl,
                             const float* __restrict__ bl,
                             float* __restrict__ out)
{
    int gwarp = (blockIdx.x * blockDim.x + threadIdx.x) >> 5;
    int lane  = threadIdx.x & 31;
    if (gwarp >= N_TOK) return;

    const float4* hv = (const float4*)(h + (size_t)gwarp * DH);
    const float4* w0 = (const float4*)(wl);
    const float4* w1 = (const float4*)(wl + DH);

    float s0 = 0.0f, s1 = 0.0f;
    for (int j = lane; j < DH / 4; j += 32) {
        float4 a  = hv[j];
        float4 c0 = w0[j];
        float4 c1 = w1[j];
        s0 += a.x * c0.x + a.y * c0.y + a.z * c0.z + a.w * c0.w;
        s1 += a.x * c1.x + a.y * c1.y + a.z * c1.z + a.w * c1.w;
    }
#pragma unroll
    for (int off = 16; off > 0; off >>= 1) {
        s0 += __shfl_xor_sync(0xFFFFFFFFu, s0, off);
        s1 += __shfl_xor_sync(0xFFFFFFFFu, s1, off);
    }
    if (lane == 0) {
        float z0 = s0 + bl[0];
        float z1 = s1 + bl[1];
        float mx = fmaxf(z0, z1);
        float e0 = expf(z0 - mx);
        float e1 = expf(z1 - mx);
        float inv = 1.0f / (e0 + e1);
        out[(size_t)gwarp * 2 + 0] = z0;
        out[(size_t)gwarp * 2 + 1] = z1;
        out[(size_t)2 * N_TOK + (size_t)gwarp * 2 + 0] = e0 * inv;
        out[(size_t)2 * N_TOK + (size_t)gwarp * 2 + 1] = e1 * inv;
    }
}

// ---------------------------------------------------------------------------
extern "C" void kernel_launch(void* const* d_in, const int* in_sizes, int n_in,
                              void* d_out, int out_size) {
    const float* x   = (const float*)d_in[0];
    const int*   seg = (const int*)d_in[1];      // int32 (JAX x64 disabled)
    const float* w1  = (const float*)d_in[2];
    const float* b1  = (const float*)d_in[3];
    const float* g1  = (const float*)d_in[4];
    const float* be1 = (const float*)d_in[5];
    const float* m1  = (const float*)d_in[6];
    const float* v1  = (const float*)d_in[7];
    const float* w2  = (const float*)d_in[8];
    const float* b2  = (const float*)d_in[9];
    const float* g2  = (const float*)d_in[10];
    const float* be2 = (const float*)d_in[11];
    const float* m2  = (const float*)d_in[12];
    const float* v2  = (const float*)d_in[13];
    const float* wl  = (const float*)d_in[14];
    const float* bl  = (const float*)d_in[15];
    float* out = (float*)d_out;

    __half *xe, *w1c, *w2c, *h1;
    float* h2;
    unsigned* mask;
    cudaGetSymbolAddress((void**)&xe,  g_xe);
    cudaGetSymbolAddress((void**)&w1c, g_w1);
    cudaGetSymbolAddress((void**)&w2c, g_w2);
    cudaGetSymbolAddress((void**)&h1,  g_h1);
    cudaGetSymbolAddress((void**)&h2,  g_h2);
    cudaGetSymbolAddress((void**)&mask, g_mask);

    cudaFuncSetAttribute(conv_mma_kernel,
                         cudaFuncAttributeMaxDynamicSharedMemorySize, SMEM_TOTAL);
    cudaFuncSetAttribute(wcvt_kernel,
                         cudaFuncAttributeMaxDynamicSharedMemorySize,
                         DH * KW * (int)sizeof(float));

    mask_kernel<<<(N_TOK + 255) / 256, 256>>>(seg, mask);

    {
        size_t tx = (size_t)N_TOK * CP1;
        split_x_kernel<<<(unsigned)((tx + 255) / 256), 256>>>(x, xe);
        wcvt_kernel<<<DH, 512, DIN * KW * sizeof(float)>>>(w1, w1c, DIN, CP1);
        wcvt_kernel<<<DH, 512, DH * KW * sizeof(float)>>>(w2, w2c, DH, DH);
    }

    dim3 grid(N_TOK / 128, DH / 128);   // m fastest -> B panel hot in L2
    conv_mma_kernel<<<grid, 128, SMEM_TOTAL>>>(
        xe, CP1, CP1 / 64, w1c, mask,
        b1, g1, be1, m1, v1, 0, nullptr, h1);
    conv_mma_kernel<<<grid, 128, SMEM_TOTAL>>>(
        h1, DH, DH / 64, w2c, mask,
        b2, g2, be2, m2, v2, 1, h2, nullptr);

    final_kernel<<<(N_TOK * 32 + 127) / 128, 128>>>(h2, wl, bl, out);
}